// round 6
// baseline (speedup 1.0000x reference)
#include <cuda_runtime.h>
#include <cstdint>
#include <cstddef>

// ---------------------------------------------------------------------------
// RSSM scan: B=256, T=64, A=64, E=1024, HID=1024, DET=2048, STO=256
// mma.sync tf32, CTA tile 128x128, 4-stage cp.async, persistent scan kernel.
// ---------------------------------------------------------------------------

#define Bv   256
#define Tv   64
#define BTv  (Bv*Tv)          // 16384
#define Av   64
#define Ev   1024
#define HIDv 1024
#define DETv 2048
#define STOv 256

#define BM 128
#define BN 128
#define BK 16
#define NSTAGE 4
#define ASTR 20
#define DYN_SMEM (NSTAGE * (BM * ASTR + BN * ASTR) * 4)   // 81920 B

// ------------------------- device scratch (no allocs) ----------------------
__device__ __align__(16) float g_Pobs[BTv * HIDv];    // obs proj (exact); rf (rounded) later
__device__ __align__(16) float g_pre [BTv * HIDv];    // action part of rnn_in + bias (exact)
__device__ __align__(16) float g_hr  [BTv * DETv];    // tf32-rounded h sequence (GEMM A)
__device__ __align__(16) float g_zr  [Bv * STOv];     // tf32-rounded z (current step)
__device__ __align__(16) float g_rnn [Bv * HIDv];     // rounded
__device__ __align__(16) float g_gi  [Bv * 3 * DETv];
__device__ __align__(16) float g_gh  [2 * Bv * 3 * DETv];   // 2 K-halves
__device__ __align__(16) float g_pf  [Bv * HIDv];     // rounded
__device__ __align__(16) float g_p4  [4 * Bv * HIDv];
__device__ __align__(16) float g_p5  [4 * Bv * 2 * STOv];
__device__ __align__(16) float g_zero[DETv];          // stays zero
// pre-rounded tf32 weights, all [N,K] row-major (K contiguous)
__device__ __align__(16) float g_WrnnT    [HIDv * (STOv + Av)];
__device__ __align__(16) float g_WpostT   [HIDv * (DETv + Ev)];
__device__ __align__(16) float g_WpostmsT [2 * STOv * HIDv];
__device__ __align__(16) float g_WpriorT  [HIDv * DETv];
__device__ __align__(16) float g_WpriormsT[2 * STOv * HIDv];
__device__ __align__(16) float g_WihR     [3 * DETv * HIDv];
__device__ __align__(16) float g_WhhR     [3 * DETv * DETv];
__device__ unsigned g_barcnt;
__device__ unsigned g_bargen;

// ------------------------------- helpers -----------------------------------
__device__ __forceinline__ float to_tf32(float x) {
    uint32_t u;
    asm("cvt.rna.tf32.f32 %0, %1;" : "=r"(u) : "f"(x));
    return __uint_as_float(u);
}
__device__ __forceinline__ uint32_t cvt_tf32(float x) {
    uint32_t u;
    asm("cvt.rna.tf32.f32 %0, %1;" : "=r"(u) : "f"(x));
    return u;
}
__device__ __forceinline__ float softplusf(float x) {
    return (x > 20.f) ? x : log1pf(expf(x));
}
__device__ __forceinline__ float sigmoidf(float x) {
    return 1.f / (1.f + expf(-x));
}
__device__ __forceinline__ uint32_t smem_u32(const void* p) {
    uint32_t a;
    asm("{ .reg .u64 t; cvta.to.shared.u64 t, %1; cvt.u32.u64 %0, t; }"
        : "=r"(a) : "l"(p));
    return a;
}
__device__ __forceinline__ void cpa16(uint32_t dst, const float* src) {
    size_t g = __cvta_generic_to_global((const void*)src);
    asm volatile("cp.async.cg.shared.global [%0], [%1], 16;"
                 :: "r"(dst), "l"(g) : "memory");
}
__device__ __forceinline__ void cpa_commit() {
    asm volatile("cp.async.commit_group;" ::: "memory");
}
__device__ __forceinline__ void mma8(float c[4], const uint32_t a[4], const uint32_t b[2]) {
    asm volatile(
        "mma.sync.aligned.m16n8k8.row.col.f32.tf32.tf32.f32 "
        "{%0,%1,%2,%3},{%4,%5,%6,%7},{%8,%9},{%0,%1,%2,%3};\n"
        : "+f"(c[0]), "+f"(c[1]), "+f"(c[2]), "+f"(c[3])
        : "r"(a[0]), "r"(a[1]), "r"(a[2]), "r"(a[3]), "r"(b[0]), "r"(b[1]));
}

// ---------------------------- grid-wide barrier -----------------------------
__device__ __forceinline__ void gridbar(int nb) {
    __syncthreads();
    if (threadIdx.x == 0) {
        __threadfence();
        unsigned gen;
        asm volatile("ld.acquire.gpu.u32 %0, [%1];" : "=r"(gen) : "l"(&g_bargen) : "memory");
        unsigned arr = atomicAdd(&g_barcnt, 1u);
        if (arr == (unsigned)nb - 1u) {
            atomicExch(&g_barcnt, 0u);
            __threadfence();
            atomicAdd(&g_bargen, 1u);
        } else {
            unsigned cur;
            do {
                asm volatile("ld.acquire.gpu.u32 %0, [%1];" : "=r"(cur) : "l"(&g_bargen) : "memory");
            } while (cur == gen);
        }
        __threadfence();
    }
    __syncthreads();
}

// ------------------------------- GEMM core ----------------------------------
// acc[128x128] = A[M,K](row-major,lda) x B[N,K](row-major,ldb, tf32-rounded).
// ACVT: round A in-register (for raw fp32 inputs). ROWMASK: (row&63)==0 -> 0.
// 256 threads, 8 warps (4m x 2n), warp tile 32x64.

template <bool ACVT>
__device__ __forceinline__ void compute_stage(const float* sa, const float* sb,
                                              float acc[2][8][4]) {
    const int lane = threadIdx.x & 31, w = threadIdx.x >> 5;
    const int wm = w >> 1, wn = w & 1;
    const int g = lane >> 2, tig = lane & 3;
#pragma unroll
    for (int kk = 0; kk < BK; kk += 8) {
        uint32_t af[2][4], bf[8][2];
#pragma unroll
        for (int mf = 0; mf < 2; mf++) {
            int mr = wm * 32 + mf * 16 + g;
            if (ACVT) {
                af[mf][0] = cvt_tf32(sa[mr * ASTR + kk + tig]);
                af[mf][1] = cvt_tf32(sa[(mr + 8) * ASTR + kk + tig]);
                af[mf][2] = cvt_tf32(sa[mr * ASTR + kk + tig + 4]);
                af[mf][3] = cvt_tf32(sa[(mr + 8) * ASTR + kk + tig + 4]);
            } else {
                af[mf][0] = __float_as_uint(sa[mr * ASTR + kk + tig]);
                af[mf][1] = __float_as_uint(sa[(mr + 8) * ASTR + kk + tig]);
                af[mf][2] = __float_as_uint(sa[mr * ASTR + kk + tig + 4]);
                af[mf][3] = __float_as_uint(sa[(mr + 8) * ASTR + kk + tig + 4]);
            }
        }
#pragma unroll
        for (int nf = 0; nf < 8; nf++) {
            int nc = wn * 64 + nf * 8 + g;
            bf[nf][0] = __float_as_uint(sb[nc * ASTR + kk + tig]);
            bf[nf][1] = __float_as_uint(sb[nc * ASTR + kk + tig + 4]);
        }
#pragma unroll
        for (int mf = 0; mf < 2; mf++)
#pragma unroll
            for (int nf = 0; nf < 8; nf++) mma8(acc[mf][nf], af[mf], bf[nf]);
    }
}

template <bool ACVT, bool ROWMASK>
__device__ void gemm_cp(float* smem, const float* __restrict__ A, int lda,
                        const float* __restrict__ B, int ldb,
                        int K, int bm0, int bn0, float acc[2][8][4]) {
    float* sa = smem;
    float* sb = smem + NSTAGE * BM * ASTR;
    const uint32_t sa_u = smem_u32(sa), sb_u = smem_u32(sb);
    const int tid = threadIdx.x;

#pragma unroll
    for (int i = 0; i < 2; i++)
#pragma unroll
        for (int j = 0; j < 8; j++)
#pragma unroll
            for (int c = 0; c < 4; c++) acc[i][j][c] = 0.f;

    auto load_stage = [&](int s, int k0) {
#pragma unroll
        for (int i = 0; i < 2; i++) {
            int idx = tid + (i << 8);
            int row = idx >> 2, kc = (idx & 3) << 2;
            int grow = bm0 + row;
            const float* src = (ROWMASK && ((grow & 63) == 0))
                                   ? (g_zero + kc)
                                   : (A + (size_t)grow * lda + k0 + kc);
            cpa16(sa_u + (uint32_t)(s * BM * ASTR + row * ASTR + kc) * 4u, src);
        }
#pragma unroll
        for (int i = 0; i < 2; i++) {
            int idx = tid + (i << 8);
            int row = idx >> 2, kc = (idx & 3) << 2;
            cpa16(sb_u + (uint32_t)(s * BN * ASTR + row * ASTR + kc) * 4u,
                  B + (size_t)(bn0 + row) * ldb + k0 + kc);
        }
        cpa_commit();
    };

    const int nk = K >> 4;
#pragma unroll
    for (int s = 0; s < NSTAGE - 1; s++) {
        if (s < nk) load_stage(s, s << 4);
        else cpa_commit();
    }
    for (int kt = 0; kt < nk; kt++) {
        asm volatile("cp.async.wait_group %0;" :: "n"(NSTAGE - 2) : "memory");
        __syncthreads();
        int kn = kt + NSTAGE - 1;
        if (kn < nk) load_stage(kn & (NSTAGE - 1), kn << 4);
        else cpa_commit();
        compute_stage<ACVT>(sa + (kt & (NSTAGE - 1)) * BM * ASTR,
                            sb + (kt & (NSTAGE - 1)) * BN * ASTR, acc);
    }
    __syncthreads();
}

template <typename F>
__device__ __forceinline__ void epi_apply(int bm0, int bn0, float acc[2][8][4], F&& f) {
    const int tid = threadIdx.x;
    const int lane = tid & 31, w = tid >> 5;
    const int wm = w >> 1, wn = w & 1;
    const int g = lane >> 2, tig = lane & 3;
#pragma unroll
    for (int mf = 0; mf < 2; mf++)
#pragma unroll
        for (int nf = 0; nf < 8; nf++)
#pragma unroll
            for (int cc = 0; cc < 4; cc++) {
                int row = bm0 + wm * 32 + mf * 16 + g + ((cc & 2) ? 8 : 0);
                int col = bn0 + wn * 64 + nf * 8 + tig * 2 + (cc & 1);
                f(row, col, acc[mf][nf][cc]);
            }
}

// -------------------------- weight prep kernels ------------------------------
__device__ __forceinline__ void do_transpose(const float* src, float* dst,
                                             int R, int C, int bx, int by) {
    __shared__ float tile[32][33];
    int rb = bx * 32, cb = by * 32;
    int x = threadIdx.x & 31, y = threadIdx.x >> 5;
#pragma unroll
    for (int i = 0; i < 32; i += 8)
        tile[y + i][x] = src[(size_t)(rb + y + i) * C + cb + x];
    __syncthreads();
#pragma unroll
    for (int i = 0; i < 32; i += 8)
        dst[(size_t)(cb + y + i) * R + rb + x] = to_tf32(tile[x][y + i]);
}

__global__ __launch_bounds__(256)
void transpose_k(const float* __restrict__ src, float* __restrict__ dst, int R, int C) {
    do_transpose(src, dst, R, C, blockIdx.x, blockIdx.y);
}

// combined: Wpost_ms^T, Wprior_ms^T transposes + Wih, Whh round-copies
__global__ __launch_bounds__(256)
void wrest_k(const float* __restrict__ Wpost_ms, const float* __restrict__ Wprior_ms,
             const float* __restrict__ Wih, const float* __restrict__ Whh) {
    int b = blockIdx.x;
    if (b < 512) {                 // Wpost_ms [1024, 512] -> T
        do_transpose(Wpost_ms, g_WpostmsT, HIDv, 2 * STOv, b & 31, b >> 5);
    } else if (b < 1024) {
        b -= 512;
        do_transpose(Wprior_ms, g_WpriormsT, HIDv, 2 * STOv, b & 31, b >> 5);
    } else if (b < 1024 + 6144) {  // Wih round-copy (6144 blocks x 1024 elts)
        int i = (b - 1024) * 1024 + threadIdx.x * 4;
        float4 v = *reinterpret_cast<const float4*>(Wih + i);
        v.x = to_tf32(v.x); v.y = to_tf32(v.y); v.z = to_tf32(v.z); v.w = to_tf32(v.w);
        *reinterpret_cast<float4*>(g_WihR + i) = v;
    } else {                       // Whh round-copy (12288 blocks)
        size_t i = (size_t)(b - 1024 - 6144) * 1024 + threadIdx.x * 4;
        float4 v = *reinterpret_cast<const float4*>(Whh + i);
        v.x = to_tf32(v.x); v.y = to_tf32(v.y); v.z = to_tf32(v.z); v.w = to_tf32(v.w);
        *reinterpret_cast<float4*>(g_WhhR + i) = v;
    }
}

// --------------------------- batched pre / post -----------------------------
__global__ __launch_bounds__(256, 2)
void prep_k(const float* __restrict__ obs, const float* __restrict__ act,
            const float* __restrict__ bpost_in, const float* __restrict__ brnn) {
    extern __shared__ float dyn[];
    float acc[2][8][4];
    int tile = blockIdx.x;
    if (tile < 1024) {   // Pobs (exact): 128 m x 8 n, K=1024
        int bm0 = (tile & 127) << 7, bn0 = (tile >> 7) << 7;
        gemm_cp<true, false>(dyn, obs, Ev, g_WpostT + DETv, DETv + Ev, Ev, bm0, bn0, acc);
        epi_apply(bm0, bn0, acc, [&](int r, int c, float v) {
            g_Pobs[(size_t)r * HIDv + c] = v + bpost_in[c];
        });
    } else {             // pre (exact): prev_actions part, K=64, row-masked
        tile -= 1024;
        int bm0 = (tile & 127) << 7, bn0 = (tile >> 7) << 7;
        gemm_cp<true, true>(dyn, act - Av, Av, g_WrnnT + STOv, STOv + Av, Av, bm0, bn0, acc);
        epi_apply(bm0, bn0, acc, [&](int r, int c, float v) {
            g_pre[(size_t)r * HIDv + c] = v + brnn[c];
        });
    }
}

__global__ __launch_bounds__(256, 2)
void rf_k(const float* __restrict__ bprior_in) {
    extern __shared__ float dyn[];
    float acc[2][8][4];
    int tile = blockIdx.x;   // 1024 tiles
    int bm0 = (tile & 127) << 7, bn0 = (tile >> 7) << 7;
    gemm_cp<false, false>(dyn, g_hr, DETv, g_WpriorT, DETv, DETv, bm0, bn0, acc);
    epi_apply(bm0, bn0, acc, [&](int r, int c, float v) {
        g_Pobs[(size_t)r * HIDv + c] = to_tf32(fmaxf(v + bprior_in[c], 0.f));
    });
}

__global__ __launch_bounds__(256, 2)
void ms_k(const float* __restrict__ bprior_ms,
          float* __restrict__ qm_o, float* __restrict__ qs_o) {
    extern __shared__ float dyn[];
    float acc[2][8][4];
    int tile = blockIdx.x;   // 512 tiles: 128 m x 4 n
    int bm0 = (tile & 127) << 7, bn0 = (tile >> 7) << 7;
    gemm_cp<false, false>(dyn, g_Pobs, HIDv, g_WpriormsT, HIDv, HIDv, bm0, bn0, acc);
    if (bn0 < STOv) {
        epi_apply(bm0, bn0, acc, [&](int r, int c, float v) {
            qm_o[(size_t)r * STOv + c] = v + bprior_ms[c];
        });
    } else {
        epi_apply(bm0, bn0, acc, [&](int r, int c, float v) {
            qs_o[(size_t)r * STOv + (c - STOv)] = softplusf(v + bprior_ms[c]) + 0.1f;
        });
    }
}

// --------------------------- persistent scan kernel -------------------------
struct ScanArgs {
    const float* noise;
    const float* bih; const float* bhh;
    const float* bpost_ms;
    float* h_o; float* z_o; float* pm_o; float* ps_o;
    int nb;
};

__global__ __launch_bounds__(256, 2)
void scan_k(ScanArgs a) {
    extern __shared__ float dyn[];
    const int nb = a.nb;
    float acc[2][8][4];
    const size_t GHS = (size_t)Bv * 3 * DETv;

    for (int t = 0; t < Tv; t++) {
        // ---- P1: rnn = relu(z_prev @ Wz^T + pre_t)  (16 tiles, K=256)
        {
            const float* Az = t ? g_zr : g_zero;
            int ldz = t ? STOv : 0;
            for (int tile = blockIdx.x; tile < 16; tile += nb) {
                int bm0 = (tile & 1) << 7, bn0 = (tile >> 1) << 7;
                gemm_cp<false, false>(dyn, Az, ldz, g_WrnnT, STOv + Av, STOv, bm0, bn0, acc);
                epi_apply(bm0, bn0, acc, [&](int r, int c, float v) {
                    v += g_pre[((size_t)r * Tv + t) * HIDv + c];
                    g_rnn[(size_t)r * HIDv + c] = to_tf32(fmaxf(v, 0.f));
                });
            }
        }
        gridbar(nb);

        // ---- P2: 288 tiles, all K=1024:
        //   0..95    gi = rnn @ Wih^T          (+bih in epi)
        //   96..287  gh half kh = hprev[:,kh*1024:] @ Whh[:,kh*1024:]^T partials
        {
            const float* Ah = t ? g_hr + (size_t)(t - 1) * DETv : g_zero;
            int ldh = t ? Tv * DETv : 0;
            for (int tile = blockIdx.x; tile < 288; tile += nb) {
                if (tile < 96) {
                    int bm0 = (tile & 1) << 7, bn0 = (tile >> 1) << 7;
                    gemm_cp<false, false>(dyn, g_rnn, HIDv, g_WihR, HIDv, HIDv, bm0, bn0, acc);
                    epi_apply(bm0, bn0, acc, [&](int r, int c, float v) {
                        g_gi[(size_t)r * (3 * DETv) + c] = v + a.bih[c];
                    });
                } else {
                    int u = tile - 96, kh = u / 96, v2 = u % 96;
                    int bm0 = (v2 & 1) << 7, bn0 = (v2 >> 1) << 7;
                    float* outp = g_gh + (size_t)kh * GHS;
                    gemm_cp<false, false>(dyn, Ah + kh * 1024, ldh,
                                          g_WhhR + kh * 1024, DETv, 1024, bm0, bn0, acc);
                    epi_apply(bm0, bn0, acc, [&](int r, int c, float v) {
                        outp[(size_t)r * (3 * DETv) + c] = v;
                    });
                }
            }
        }
        gridbar(nb);

        // ---- P3: GRU elementwise -> h_t (exact) + g_hr (rounded)
        {
            const float* hp = t ? a.h_o + (size_t)(t - 1) * DETv : g_zero;
            int hps = t ? Tv * DETv : 0;
            for (int i = blockIdx.x * 256 + threadIdx.x; i < Bv * DETv; i += nb * 256) {
                int m = i >> 11, j = i & 2047;
                size_t base = (size_t)m * (3 * DETv);
                float gh0 = g_gh[base + j] + g_gh[GHS + base + j] + a.bhh[j];
                float gh1 = g_gh[base + DETv + j] + g_gh[GHS + base + DETv + j] + a.bhh[DETv + j];
                float gh2 = g_gh[base + 2 * DETv + j] + g_gh[GHS + base + 2 * DETv + j] + a.bhh[2 * DETv + j];
                float r = sigmoidf(g_gi[base + j] + gh0);
                float u = sigmoidf(g_gi[base + DETv + j] + gh1);
                float n = tanhf(g_gi[base + 2 * DETv + j] + r * gh2);
                float hv = (1.f - u) * n + u * hp[(size_t)m * hps + j];
                size_t o = ((size_t)m * Tv + t) * DETv + j;
                a.h_o[o] = hv;
                g_hr[o] = to_tf32(hv);
            }
        }
        gridbar(nb);

        // ---- P4a: pf split-K partials (64 tiles: 4ks x 2m x 8n, K=512)
        for (int tile = blockIdx.x; tile < 64; tile += nb) {
            int ks = tile >> 4, rem = tile & 15;
            int bm0 = (rem & 1) << 7, bn0 = (rem >> 1) << 7;
            gemm_cp<false, false>(dyn, g_hr + (size_t)t * DETv + ks * 512, Tv * DETv,
                                  g_WpostT + ks * 512, DETv + Ev, 512, bm0, bn0, acc);
            epi_apply(bm0, bn0, acc, [&](int r, int c, float v) {
                g_p4[(size_t)ks * Bv * HIDv + (size_t)r * HIDv + c] = v;
            });
        }
        gridbar(nb);

        // ---- P4b: reduce + Pobs + relu -> pf (rounded)
        for (int i = blockIdx.x * 256 + threadIdx.x; i < Bv * HIDv; i += nb * 256) {
            int m = i >> 10, j = i & 1023;
            float v = g_p4[i] + g_p4[(size_t)Bv * HIDv + i] +
                      g_p4[2 * (size_t)Bv * HIDv + i] + g_p4[3 * (size_t)Bv * HIDv + i];
            v += g_Pobs[((size_t)m * Tv + t) * HIDv + j];
            g_pf[i] = to_tf32(fmaxf(v, 0.f));
        }
        gridbar(nb);

        // ---- P5a: [pm|ps] split-K partials (32 tiles: 4ks x 2m x 4n, K=256)
        for (int tile = blockIdx.x; tile < 32; tile += nb) {
            int ks = tile >> 3, rem = tile & 7;
            int bm0 = (rem & 1) << 7, bn0 = (rem >> 1) << 7;
            gemm_cp<false, false>(dyn, g_pf + ks * 256, HIDv,
                                  g_WpostmsT + ks * 256, HIDv, 256, bm0, bn0, acc);
            epi_apply(bm0, bn0, acc, [&](int r, int c, float v) {
                g_p5[(size_t)ks * Bv * (2 * STOv) + (size_t)r * (2 * STOv) + c] = v;
            });
        }
        gridbar(nb);

        // ---- P5b: pm, ps, z (exact) + g_zr (rounded)
        for (int i = blockIdx.x * 256 + threadIdx.x; i < Bv * STOv; i += nb * 256) {
            int m = i >> 8, j = i & 255;
            size_t b0 = (size_t)m * (2 * STOv);
            const size_t S = (size_t)Bv * (2 * STOv);
            float pm = g_p5[b0 + j] + g_p5[S + b0 + j] + g_p5[2 * S + b0 + j] +
                       g_p5[3 * S + b0 + j] + a.bpost_ms[j];
            float sr = g_p5[b0 + STOv + j] + g_p5[S + b0 + STOv + j] +
                       g_p5[2 * S + b0 + STOv + j] + g_p5[3 * S + b0 + STOv + j] +
                       a.bpost_ms[STOv + j];
            float ps = softplusf(sr) + 0.1f;
            size_t o = ((size_t)m * Tv + t) * STOv + j;
            float z = pm + ps * a.noise[o];
            a.pm_o[o] = pm;
            a.ps_o[o] = ps;
            a.z_o[o] = z;
            g_zr[i] = to_tf32(z);
        }
        gridbar(nb);
    }
}

// ------------------------------- launch -------------------------------------
extern "C" void kernel_launch(void* const* d_in, const int* in_sizes, int n_in,
                              void* d_out, int out_size) {
    const float* obs      = (const float*)d_in[0];
    const float* act      = (const float*)d_in[1];
    const float* noise    = (const float*)d_in[4];
    const float* Wrnn     = (const float*)d_in[5];
    const float* brnn     = (const float*)d_in[6];
    const float* Wih      = (const float*)d_in[7];
    const float* Whh      = (const float*)d_in[8];
    const float* bih      = (const float*)d_in[9];
    const float* bhh      = (const float*)d_in[10];
    const float* Wpost_in = (const float*)d_in[11];
    const float* bpost_in = (const float*)d_in[12];
    const float* Wpost_ms = (const float*)d_in[13];
    const float* bpost_ms = (const float*)d_in[14];
    const float* Wprior_in= (const float*)d_in[15];
    const float* bprior_in= (const float*)d_in[16];
    const float* Wprior_ms= (const float*)d_in[17];
    const float* bprior_ms= (const float*)d_in[18];

    float* out  = (float*)d_out;
    float* h_o  = out;
    float* z_o  = h_o + (size_t)BTv * DETv;
    float* pm_o = z_o + (size_t)BTv * STOv;
    float* ps_o = pm_o + (size_t)BTv * STOv;
    float* qm_o = ps_o + (size_t)BTv * STOv;
    float* qs_o = qm_o + (size_t)BTv * STOv;

    cudaFuncSetAttribute(prep_k, cudaFuncAttributeMaxDynamicSharedMemorySize, DYN_SMEM);
    cudaFuncSetAttribute(rf_k,   cudaFuncAttributeMaxDynamicSharedMemorySize, DYN_SMEM);
    cudaFuncSetAttribute(ms_k,   cudaFuncAttributeMaxDynamicSharedMemorySize, DYN_SMEM);
    cudaFuncSetAttribute(scan_k, cudaFuncAttributeMaxDynamicSharedMemorySize, DYN_SMEM);

    float *WrnnT, *WpostT, *WpriorT;
    cudaGetSymbolAddress((void**)&WrnnT,  g_WrnnT);
    cudaGetSymbolAddress((void**)&WpostT, g_WpostT);
    cudaGetSymbolAddress((void**)&WpriorT,g_WpriorT);

    // launches (per replay): 0..2 transposes, 3 wrest, 4 prep, 5 scan, 6 rf, 7 ms
    transpose_k<<<dim3((STOv + Av) / 32, HIDv / 32), 256>>>(Wrnn, WrnnT, STOv + Av, HIDv);
    transpose_k<<<dim3((DETv + Ev) / 32, HIDv / 32), 256>>>(Wpost_in, WpostT, DETv + Ev, HIDv);
    transpose_k<<<dim3(DETv / 32, HIDv / 32), 256>>>(Wprior_in, WpriorT, DETv, HIDv);
    wrest_k<<<1024 + 6144 + 12288, 256>>>(Wpost_ms, Wprior_ms, Wih, Whh);

    prep_k<<<2048, 256, DYN_SMEM>>>(obs, act, bpost_in, brnn);

    int nsm = 0, maxb = 0;
    cudaDeviceGetAttribute(&nsm, cudaDevAttrMultiProcessorCount, 0);
    cudaOccupancyMaxActiveBlocksPerMultiprocessor(&maxb, scan_k, 256, DYN_SMEM);
    if (maxb > 2) maxb = 2;
    if (maxb < 1) maxb = 1;
    int nb = nsm * maxb;

    ScanArgs a;
    a.noise = noise;
    a.bih = bih; a.bhh = bhh;
    a.bpost_ms = bpost_ms;
    a.h_o = h_o; a.z_o = z_o; a.pm_o = pm_o; a.ps_o = ps_o;
    a.nb = nb;
    scan_k<<<nb, 256, DYN_SMEM>>>(a);

    rf_k<<<1024, 256, DYN_SMEM>>>(bprior_in);
    ms_k<<<512, 256, DYN_SMEM>>>(bprior_ms, qm_o, qs_o);
}

// round 8
// speedup vs baseline: 1.4052x; 1.4052x over previous
#include <cuda_runtime.h>
#include <cstdint>
#include <cstddef>

// ---------------------------------------------------------------------------
// RSSM scan: B=256, T=64, A=64, E=1024, HID=1024, DET=2048, STO=256
// mma.sync tf32, CTA tile 128x64, 4-stage cp.async, persistent scan kernel.
// ---------------------------------------------------------------------------

#define Bv   256
#define Tv   64
#define BTv  (Bv*Tv)          // 16384
#define Av   64
#define Ev   1024
#define HIDv 1024
#define DETv 2048
#define STOv 256

#define BM 128
#define BN 64
#define BK 16
#define NSTAGE 4
#define ASTR 20
#define DYN_SMEM (NSTAGE * (BM * ASTR + BN * ASTR) * 4)   // 61440 B

// ------------------------- device scratch (no allocs) ----------------------
__device__ __align__(16) float g_Pobs[BTv * HIDv];    // obs proj (exact); rf (rounded) later
__device__ __align__(16) float g_pre [BTv * HIDv];    // action part of rnn_in + bias (exact)
__device__ __align__(16) float g_hr  [BTv * DETv];    // tf32-rounded h sequence (GEMM A)
__device__ __align__(16) float g_zr  [Bv * STOv];     // tf32-rounded z (current step)
__device__ __align__(16) float g_rnn [Bv * HIDv];     // rounded
__device__ __align__(16) float g_gi  [Bv * 3 * DETv];
__device__ __align__(16) float g_gh  [2 * Bv * 3 * DETv];   // 2 K-halves
__device__ __align__(16) float g_pf  [Bv * HIDv];     // rounded
__device__ __align__(16) float g_p4  [4 * Bv * HIDv];
__device__ __align__(16) float g_p5  [4 * Bv * 2 * STOv];
__device__ __align__(16) float g_zero[DETv];          // stays zero
// pre-rounded tf32 weights, all [N,K] row-major (K contiguous)
__device__ __align__(16) float g_WrnnT    [HIDv * (STOv + Av)];
__device__ __align__(16) float g_WpostT   [HIDv * (DETv + Ev)];
__device__ __align__(16) float g_WpostmsT [2 * STOv * HIDv];
__device__ __align__(16) float g_WpriorT  [HIDv * DETv];
__device__ __align__(16) float g_WpriormsT[2 * STOv * HIDv];
__device__ __align__(16) float g_WihR     [3 * DETv * HIDv];
__device__ __align__(16) float g_WhhR     [3 * DETv * DETv];
__device__ unsigned g_barcnt;
__device__ unsigned g_bargen;

// ------------------------------- helpers -----------------------------------
__device__ __forceinline__ float to_tf32(float x) {
    uint32_t u;
    asm("cvt.rna.tf32.f32 %0, %1;" : "=r"(u) : "f"(x));
    return __uint_as_float(u);
}
__device__ __forceinline__ uint32_t cvt_tf32(float x) {
    uint32_t u;
    asm("cvt.rna.tf32.f32 %0, %1;" : "=r"(u) : "f"(x));
    return u;
}
__device__ __forceinline__ float softplusf(float x) {
    return (x > 20.f) ? x : log1pf(expf(x));
}
__device__ __forceinline__ float sigmoidf(float x) {
    return 1.f / (1.f + expf(-x));
}
__device__ __forceinline__ uint32_t smem_u32(const void* p) {
    uint32_t a;
    asm("{ .reg .u64 t; cvta.to.shared.u64 t, %1; cvt.u32.u64 %0, t; }"
        : "=r"(a) : "l"(p));
    return a;
}
__device__ __forceinline__ void cpa16(uint32_t dst, const float* src) {
    size_t g = __cvta_generic_to_global((const void*)src);
    asm volatile("cp.async.cg.shared.global [%0], [%1], 16;"
                 :: "r"(dst), "l"(g) : "memory");
}
__device__ __forceinline__ void cpa_commit() {
    asm volatile("cp.async.commit_group;" ::: "memory");
}
__device__ __forceinline__ void mma8(float c[4], const uint32_t a[4], const uint32_t b[2]) {
    asm volatile(
        "mma.sync.aligned.m16n8k8.row.col.f32.tf32.tf32.f32 "
        "{%0,%1,%2,%3},{%4,%5,%6,%7},{%8,%9},{%0,%1,%2,%3};\n"
        : "+f"(c[0]), "+f"(c[1]), "+f"(c[2]), "+f"(c[3])
        : "r"(a[0]), "r"(a[1]), "r"(a[2]), "r"(a[3]), "r"(b[0]), "r"(b[1]));
}

// ---------------------------- grid-wide barrier -----------------------------
__device__ __forceinline__ void gridbar(int nb) {
    __syncthreads();
    if (threadIdx.x == 0) {
        __threadfence();
        unsigned gen;
        asm volatile("ld.acquire.gpu.u32 %0, [%1];" : "=r"(gen) : "l"(&g_bargen) : "memory");
        unsigned arr = atomicAdd(&g_barcnt, 1u);
        if (arr == (unsigned)nb - 1u) {
            atomicExch(&g_barcnt, 0u);
            __threadfence();
            atomicAdd(&g_bargen, 1u);
        } else {
            unsigned cur;
            do {
                asm volatile("ld.acquire.gpu.u32 %0, [%1];" : "=r"(cur) : "l"(&g_bargen) : "memory");
            } while (cur == gen);
        }
        __threadfence();
    }
    __syncthreads();
}

// ------------------------------- GEMM core ----------------------------------
// acc[128x64] = A[M,K](row-major,lda) x B[N,K](row-major,ldb, tf32-rounded).
// ACVT: round A in-register (raw fp32 inputs only). ROWMASK: (row&63)==0 -> 0.
// 256 threads, 8 warps (4m x 2n), warp tile 32x32.

template <bool ACVT>
__device__ __forceinline__ void compute_stage(const float* sa, const float* sb,
                                              float acc[2][4][4]) {
    const int lane = threadIdx.x & 31, w = threadIdx.x >> 5;
    const int wm = w >> 1, wn = w & 1;
    const int g = lane >> 2, tig = lane & 3;
#pragma unroll
    for (int kk = 0; kk < BK; kk += 8) {
        uint32_t af[2][4], bf[4][2];
#pragma unroll
        for (int mf = 0; mf < 2; mf++) {
            int mr = wm * 32 + mf * 16 + g;
            if (ACVT) {
                af[mf][0] = cvt_tf32(sa[mr * ASTR + kk + tig]);
                af[mf][1] = cvt_tf32(sa[(mr + 8) * ASTR + kk + tig]);
                af[mf][2] = cvt_tf32(sa[mr * ASTR + kk + tig + 4]);
                af[mf][3] = cvt_tf32(sa[(mr + 8) * ASTR + kk + tig + 4]);
            } else {
                af[mf][0] = __float_as_uint(sa[mr * ASTR + kk + tig]);
                af[mf][1] = __float_as_uint(sa[(mr + 8) * ASTR + kk + tig]);
                af[mf][2] = __float_as_uint(sa[mr * ASTR + kk + tig + 4]);
                af[mf][3] = __float_as_uint(sa[(mr + 8) * ASTR + kk + tig + 4]);
            }
        }
#pragma unroll
        for (int nf = 0; nf < 4; nf++) {
            int nc = wn * 32 + nf * 8 + g;
            bf[nf][0] = __float_as_uint(sb[nc * ASTR + kk + tig]);
            bf[nf][1] = __float_as_uint(sb[nc * ASTR + kk + tig + 4]);
        }
#pragma unroll
        for (int mf = 0; mf < 2; mf++)
#pragma unroll
            for (int nf = 0; nf < 4; nf++) mma8(acc[mf][nf], af[mf], bf[nf]);
    }
}

template <bool ACVT, bool ROWMASK>
__device__ void gemm_cp(float* smem, const float* __restrict__ A, int lda,
                        const float* __restrict__ B, int ldb,
                        int K, int bm0, int bn0, float acc[2][4][4]) {
    float* sa = smem;
    float* sb = smem + NSTAGE * BM * ASTR;
    const uint32_t sa_u = smem_u32(sa), sb_u = smem_u32(sb);
    const int tid = threadIdx.x;

#pragma unroll
    for (int i = 0; i < 2; i++)
#pragma unroll
        for (int j = 0; j < 4; j++)
#pragma unroll
            for (int c = 0; c < 4; c++) acc[i][j][c] = 0.f;

    auto load_stage = [&](int s, int k0) {
#pragma unroll
        for (int i = 0; i < 2; i++) {
            int idx = tid + (i << 8);
            int row = idx >> 2, kc = (idx & 3) << 2;
            int grow = bm0 + row;
            const float* src = (ROWMASK && ((grow & 63) == 0))
                                   ? (g_zero + kc)
                                   : (A + (size_t)grow * lda + k0 + kc);
            cpa16(sa_u + (uint32_t)(s * BM * ASTR + row * ASTR + kc) * 4u, src);
        }
        {
            int row = tid >> 2, kc = (tid & 3) << 2;
            cpa16(sb_u + (uint32_t)(s * BN * ASTR + row * ASTR + kc) * 4u,
                  B + (size_t)(bn0 + row) * ldb + k0 + kc);
        }
        cpa_commit();
    };

    const int nk = K >> 4;
#pragma unroll
    for (int s = 0; s < NSTAGE - 1; s++) {
        if (s < nk) load_stage(s, s << 4);
        else cpa_commit();
    }
    for (int kt = 0; kt < nk; kt++) {
        asm volatile("cp.async.wait_group %0;" :: "n"(NSTAGE - 2) : "memory");
        __syncthreads();
        int kn = kt + NSTAGE - 1;
        if (kn < nk) load_stage(kn & (NSTAGE - 1), kn << 4);
        else cpa_commit();
        compute_stage<ACVT>(sa + (kt & (NSTAGE - 1)) * BM * ASTR,
                            sb + (kt & (NSTAGE - 1)) * BN * ASTR, acc);
    }
    __syncthreads();
}

template <typename F>
__device__ __forceinline__ void epi_apply(int bm0, int bn0, float acc[2][4][4], F&& f) {
    const int tid = threadIdx.x;
    const int lane = tid & 31, w = tid >> 5;
    const int wm = w >> 1, wn = w & 1;
    const int g = lane >> 2, tig = lane & 3;
#pragma unroll
    for (int mf = 0; mf < 2; mf++)
#pragma unroll
        for (int nf = 0; nf < 4; nf++)
#pragma unroll
            for (int cc = 0; cc < 4; cc++) {
                int row = bm0 + wm * 32 + mf * 16 + g + ((cc & 2) ? 8 : 0);
                int col = bn0 + wn * 32 + nf * 8 + tig * 2 + (cc & 1);
                f(row, col, acc[mf][nf][cc]);
            }
}

// -------------------------- weight prep kernels ------------------------------
__device__ __forceinline__ void do_transpose(const float* src, float* dst,
                                             int R, int C, int bx, int by) {
    __shared__ float tile[32][33];
    int rb = bx * 32, cb = by * 32;
    int x = threadIdx.x & 31, y = threadIdx.x >> 5;
#pragma unroll
    for (int i = 0; i < 32; i += 8)
        tile[y + i][x] = src[(size_t)(rb + y + i) * C + cb + x];
    __syncthreads();
#pragma unroll
    for (int i = 0; i < 32; i += 8)
        dst[(size_t)(cb + y + i) * R + rb + x] = to_tf32(tile[x][y + i]);
}

__global__ __launch_bounds__(256)
void transpose_k(const float* __restrict__ src, float* __restrict__ dst, int R, int C) {
    do_transpose(src, dst, R, C, blockIdx.x, blockIdx.y);
}

// combined: Wpost_ms^T, Wprior_ms^T transposes + Wih, Whh round-copies
__global__ __launch_bounds__(256)
void wrest_k(const float* __restrict__ Wpost_ms, const float* __restrict__ Wprior_ms,
             const float* __restrict__ Wih, const float* __restrict__ Whh) {
    int b = blockIdx.x;
    if (b < 512) {
        do_transpose(Wpost_ms, g_WpostmsT, HIDv, 2 * STOv, b & 31, b >> 5);
    } else if (b < 1024) {
        b -= 512;
        do_transpose(Wprior_ms, g_WpriormsT, HIDv, 2 * STOv, b & 31, b >> 5);
    } else if (b < 1024 + 6144) {
        int i = (b - 1024) * 1024 + threadIdx.x * 4;
        float4 v = *reinterpret_cast<const float4*>(Wih + i);
        v.x = to_tf32(v.x); v.y = to_tf32(v.y); v.z = to_tf32(v.z); v.w = to_tf32(v.w);
        *reinterpret_cast<float4*>(g_WihR + i) = v;
    } else {
        size_t i = (size_t)(b - 1024 - 6144) * 1024 + threadIdx.x * 4;
        float4 v = *reinterpret_cast<const float4*>(Whh + i);
        v.x = to_tf32(v.x); v.y = to_tf32(v.y); v.z = to_tf32(v.z); v.w = to_tf32(v.w);
        *reinterpret_cast<float4*>(g_WhhR + i) = v;
    }
}

// --------------------------- batched pre / post -----------------------------
__global__ __launch_bounds__(256)
void prep_k(const float* __restrict__ obs, const float* __restrict__ act,
            const float* __restrict__ bpost_in, const float* __restrict__ brnn) {
    extern __shared__ float dyn[];
    float acc[2][4][4];
    int tile = blockIdx.x;
    if (tile < 2048) {   // Pobs (exact epi add target), ACVT for raw obs
        int bm0 = (tile & 127) << 7, bn0 = (tile >> 7) << 6;
        gemm_cp<true, false>(dyn, obs, Ev, g_WpostT + DETv, DETv + Ev, Ev, bm0, bn0, acc);
        epi_apply(bm0, bn0, acc, [&](int r, int c, float v) {
            g_Pobs[(size_t)r * HIDv + c] = v + bpost_in[c];
        });
    } else {             // pre: prev_actions part, K=64, row-masked
        tile -= 2048;
        int bm0 = (tile & 127) << 7, bn0 = (tile >> 7) << 6;
        gemm_cp<true, true>(dyn, act - Av, Av, g_WrnnT + STOv, STOv + Av, Av, bm0, bn0, acc);
        epi_apply(bm0, bn0, acc, [&](int r, int c, float v) {
            g_pre[(size_t)r * HIDv + c] = v + brnn[c];
        });
    }
}

__global__ __launch_bounds__(256)
void rf_k(const float* __restrict__ bprior_in) {
    extern __shared__ float dyn[];
    float acc[2][4][4];
    int tile = blockIdx.x;   // 2048 tiles
    int bm0 = (tile & 127) << 7, bn0 = (tile >> 7) << 6;
    gemm_cp<false, false>(dyn, g_hr, DETv, g_WpriorT, DETv, DETv, bm0, bn0, acc);
    epi_apply(bm0, bn0, acc, [&](int r, int c, float v) {
        g_Pobs[(size_t)r * HIDv + c] = to_tf32(fmaxf(v + bprior_in[c], 0.f));
    });
}

__global__ __launch_bounds__(256)
void ms_k(const float* __restrict__ bprior_ms,
          float* __restrict__ qm_o, float* __restrict__ qs_o) {
    extern __shared__ float dyn[];
    float acc[2][4][4];
    int tile = blockIdx.x;   // 1024 tiles: 128m x 8n
    int bm0 = (tile & 127) << 7, bn0 = (tile >> 7) << 6;
    gemm_cp<false, false>(dyn, g_Pobs, HIDv, g_WpriormsT, HIDv, HIDv, bm0, bn0, acc);
    if (bn0 < STOv) {
        epi_apply(bm0, bn0, acc, [&](int r, int c, float v) {
            qm_o[(size_t)r * STOv + c] = v + bprior_ms[c];
        });
    } else {
        epi_apply(bm0, bn0, acc, [&](int r, int c, float v) {
            qs_o[(size_t)r * STOv + (c - STOv)] = softplusf(v + bprior_ms[c]) + 0.1f;
        });
    }
}

// --------------------------- persistent scan kernel -------------------------
struct ScanArgs {
    const float* noise;
    const float* bih; const float* bhh;
    const float* bpost_ms;
    float* h_o; float* z_o; float* pm_o; float* ps_o;
    int nb;
};

__global__ __launch_bounds__(256)
void scan_k(ScanArgs a) {
    extern __shared__ float dyn[];
    const int nb = a.nb;
    float acc[2][4][4];
    const size_t GHS = (size_t)Bv * 3 * DETv;

    for (int t = 0; t < Tv; t++) {
        // ---- P1: rnn = relu(z_prev @ Wz^T + pre_t)  (32 tiles, K=256)
        {
            const float* Az = t ? g_zr : g_zero;
            int ldz = t ? STOv : 0;
            for (int tile = blockIdx.x; tile < 32; tile += nb) {
                int bm0 = (tile & 1) << 7, bn0 = (tile >> 1) << 6;
                gemm_cp<false, false>(dyn, Az, ldz, g_WrnnT, STOv + Av, STOv, bm0, bn0, acc);
                epi_apply(bm0, bn0, acc, [&](int r, int c, float v) {
                    v += g_pre[((size_t)r * Tv + t) * HIDv + c];
                    g_rnn[(size_t)r * HIDv + c] = to_tf32(fmaxf(v, 0.f));
                });
            }
        }
        gridbar(nb);

        // ---- P2: 576 uniform K=1024 tiles:
        //   0..191    gi = rnn @ Wih^T (+bih)
        //   192..575  gh half kh: hprev[:,kh*1024:] @ Whh[:,kh*1024:]^T partials
        {
            const float* Ah = t ? g_hr + (size_t)(t - 1) * DETv : g_zero;
            int ldh = t ? Tv * DETv : 0;
            for (int tile = blockIdx.x; tile < 576; tile += nb) {
                if (tile < 192) {
                    int bm0 = (tile & 1) << 7, bn0 = (tile >> 1) << 6;
                    gemm_cp<false, false>(dyn, g_rnn, HIDv, g_WihR, HIDv, HIDv, bm0, bn0, acc);
                    epi_apply(bm0, bn0, acc, [&](int r, int c, float v) {
                        g_gi[(size_t)r * (3 * DETv) + c] = v + a.bih[c];
                    });
                } else {
                    int u = tile - 192, kh = u / 192, v2 = u % 192;
                    int bm0 = (v2 & 1) << 7, bn0 = (v2 >> 1) << 6;
                    float* outp = g_gh + (size_t)kh * GHS;
                    gemm_cp<false, false>(dyn, Ah + kh * 1024, ldh,
                                          g_WhhR + kh * 1024, DETv, 1024, bm0, bn0, acc);
                    epi_apply(bm0, bn0, acc, [&](int r, int c, float v) {
                        outp[(size_t)r * (3 * DETv) + c] = v;
                    });
                }
            }
        }
        gridbar(nb);

        // ---- P3: GRU elementwise (gh reduce fused) -> h_t exact + g_hr rounded
        {
            const float* hp = t ? a.h_o + (size_t)(t - 1) * DETv : g_zero;
            int hps = t ? Tv * DETv : 0;
            for (int i = blockIdx.x * 256 + threadIdx.x; i < Bv * DETv; i += nb * 256) {
                int m = i >> 11, j = i & 2047;
                size_t base = (size_t)m * (3 * DETv);
                float gh0 = g_gh[base + j] + g_gh[GHS + base + j] + a.bhh[j];
                float gh1 = g_gh[base + DETv + j] + g_gh[GHS + base + DETv + j] + a.bhh[DETv + j];
                float gh2 = g_gh[base + 2 * DETv + j] + g_gh[GHS + base + 2 * DETv + j] + a.bhh[2 * DETv + j];
                float r = sigmoidf(g_gi[base + j] + gh0);
                float u = sigmoidf(g_gi[base + DETv + j] + gh1);
                float n = tanhf(g_gi[base + 2 * DETv + j] + r * gh2);
                float hv = (1.f - u) * n + u * hp[(size_t)m * hps + j];
                size_t o = ((size_t)m * Tv + t) * DETv + j;
                a.h_o[o] = hv;
                g_hr[o] = to_tf32(hv);
            }
        }
        gridbar(nb);

        // ---- P4a: pf split-K partials (128 tiles: 4ks x 2m x 16n, K=512)
        for (int tile = blockIdx.x; tile < 128; tile += nb) {
            int ks = tile >> 5, rem = tile & 31;
            int bm0 = (rem & 1) << 7, bn0 = (rem >> 1) << 6;
            gemm_cp<false, false>(dyn, g_hr + (size_t)t * DETv + ks * 512, Tv * DETv,
                                  g_WpostT + ks * 512, DETv + Ev, 512, bm0, bn0, acc);
            epi_apply(bm0, bn0, acc, [&](int r, int c, float v) {
                g_p4[(size_t)ks * Bv * HIDv + (size_t)r * HIDv + c] = v;
            });
        }
        gridbar(nb);

        // ---- P4b: reduce + Pobs + relu -> pf (rounded)
        for (int i = blockIdx.x * 256 + threadIdx.x; i < Bv * HIDv; i += nb * 256) {
            int m = i >> 10, j = i & 1023;
            float v = g_p4[i] + g_p4[(size_t)Bv * HIDv + i] +
                      g_p4[2 * (size_t)Bv * HIDv + i] + g_p4[3 * (size_t)Bv * HIDv + i];
            v += g_Pobs[((size_t)m * Tv + t) * HIDv + j];
            g_pf[i] = to_tf32(fmaxf(v, 0.f));
        }
        gridbar(nb);

        // ---- P5a: [pm|ps] split-K partials (64 tiles: 4ks x 2m x 8n, K=256)
        for (int tile = blockIdx.x; tile < 64; tile += nb) {
            int ks = tile >> 4, rem = tile & 15;
            int bm0 = (rem & 1) << 7, bn0 = (rem >> 1) << 6;
            gemm_cp<false, false>(dyn, g_pf + ks * 256, HIDv,
                                  g_WpostmsT + ks * 256, HIDv, 256, bm0, bn0, acc);
            epi_apply(bm0, bn0, acc, [&](int r, int c, float v) {
                g_p5[(size_t)ks * Bv * (2 * STOv) + (size_t)r * (2 * STOv) + c] = v;
            });
        }
        gridbar(nb);

        // ---- P5b: pm, ps, z exact + g_zr rounded
        for (int i = blockIdx.x * 256 + threadIdx.x; i < Bv * STOv; i += nb * 256) {
            int m = i >> 8, j = i & 255;
            size_t b0 = (size_t)m * (2 * STOv);
            const size_t S = (size_t)Bv * (2 * STOv);
            float pm = g_p5[b0 + j] + g_p5[S + b0 + j] + g_p5[2 * S + b0 + j] +
                       g_p5[3 * S + b0 + j] + a.bpost_ms[j];
            float sr = g_p5[b0 + STOv + j] + g_p5[S + b0 + STOv + j] +
                       g_p5[2 * S + b0 + STOv + j] + g_p5[3 * S + b0 + STOv + j] +
                       a.bpost_ms[STOv + j];
            float ps = softplusf(sr) + 0.1f;
            size_t o = ((size_t)m * Tv + t) * STOv + j;
            float z = pm + ps * a.noise[o];
            a.pm_o[o] = pm;
            a.ps_o[o] = ps;
            a.z_o[o] = z;
            g_zr[i] = to_tf32(z);
        }
        gridbar(nb);
    }
}

// ------------------------------- launch -------------------------------------
extern "C" void kernel_launch(void* const* d_in, const int* in_sizes, int n_in,
                              void* d_out, int out_size) {
    const float* obs      = (const float*)d_in[0];
    const float* act      = (const float*)d_in[1];
    const float* noise    = (const float*)d_in[4];
    const float* Wrnn     = (const float*)d_in[5];
    const float* brnn     = (const float*)d_in[6];
    const float* Wih      = (const float*)d_in[7];
    const float* Whh      = (const float*)d_in[8];
    const float* bih      = (const float*)d_in[9];
    const float* bhh      = (const float*)d_in[10];
    const float* Wpost_in = (const float*)d_in[11];
    const float* bpost_in = (const float*)d_in[12];
    const float* Wpost_ms = (const float*)d_in[13];
    const float* bpost_ms = (const float*)d_in[14];
    const float* Wprior_in= (const float*)d_in[15];
    const float* bprior_in= (const float*)d_in[16];
    const float* Wprior_ms= (const float*)d_in[17];
    const float* bprior_ms= (const float*)d_in[18];

    float* out  = (float*)d_out;
    float* h_o  = out;
    float* z_o  = h_o + (size_t)BTv * DETv;
    float* pm_o = z_o + (size_t)BTv * STOv;
    float* ps_o = pm_o + (size_t)BTv * STOv;
    float* qm_o = ps_o + (size_t)BTv * STOv;
    float* qs_o = qm_o + (size_t)BTv * STOv;

    cudaFuncSetAttribute(prep_k, cudaFuncAttributeMaxDynamicSharedMemorySize, DYN_SMEM);
    cudaFuncSetAttribute(rf_k,   cudaFuncAttributeMaxDynamicSharedMemorySize, DYN_SMEM);
    cudaFuncSetAttribute(ms_k,   cudaFuncAttributeMaxDynamicSharedMemorySize, DYN_SMEM);
    cudaFuncSetAttribute(scan_k, cudaFuncAttributeMaxDynamicSharedMemorySize, DYN_SMEM);

    float *WrnnT, *WpostT, *WpriorT;
    cudaGetSymbolAddress((void**)&WrnnT,  g_WrnnT);
    cudaGetSymbolAddress((void**)&WpostT, g_WpostT);
    cudaGetSymbolAddress((void**)&WpriorT,g_WpriorT);

    // launches: 0..2 transposes, 3 wrest, 4 prep, 5 scan, 6 rf, 7 ms
    transpose_k<<<dim3((STOv + Av) / 32, HIDv / 32), 256>>>(Wrnn, WrnnT, STOv + Av, HIDv);
    transpose_k<<<dim3((DETv + Ev) / 32, HIDv / 32), 256>>>(Wpost_in, WpostT, DETv + Ev, HIDv);
    transpose_k<<<dim3(DETv / 32, HIDv / 32), 256>>>(Wprior_in, WpriorT, DETv, HIDv);
    wrest_k<<<1024 + 6144 + 12288, 256>>>(Wpost_ms, Wprior_ms, Wih, Whh);

    prep_k<<<4096, 256, DYN_SMEM>>>(obs, act, bpost_in, brnn);

    int nsm = 0, maxb = 0;
    cudaDeviceGetAttribute(&nsm, cudaDevAttrMultiProcessorCount, 0);
    if (nsm <= 0) nsm = 148;
    cudaOccupancyMaxActiveBlocksPerMultiprocessor(&maxb, scan_k, 256, DYN_SMEM);
    if (maxb > 2) maxb = 2;
    if (maxb < 1) maxb = 1;
    int nb = nsm * maxb;

    ScanArgs a;
    a.noise = noise;
    a.bih = bih; a.bhh = bhh;
    a.bpost_ms = bpost_ms;
    a.h_o = h_o; a.z_o = z_o; a.pm_o = pm_o; a.ps_o = ps_o;
    a.nb = nb;
    scan_k<<<nb, 256, DYN_SMEM>>>(a);

    rf_k<<<2048, 256, DYN_SMEM>>>(bprior_in);
    ms_k<<<1024, 256, DYN_SMEM>>>(bprior_ms, qm_o, qs_o);
}

// round 9
// speedup vs baseline: 3.5745x; 2.5438x over previous
#include <cuda_runtime.h>
#include <cuda_fp16.h>
#include <cstdint>
#include <cstddef>

// ---------------------------------------------------------------------------
// RSSM scan: B=256, T=64, A=64, E=1024, HID=1024, DET=2048, STO=256
// fp16 m16n8k16 mma, fragment-packed operands, 4-stage cp.async, persistent scan.
// ---------------------------------------------------------------------------

#define Bv   256
#define Tv   64
#define BTv  (Bv*Tv)          // 16384
#define Av   64
#define Ev   1024
#define HIDv 1024
#define DETv 2048
#define STOv 256

#define BM 128
#define BN 64
#define NSTAGE 4
// smem: A stages 4*8KB + B stages 4*4KB
#define DYN_SMEM 49152

// ------------------------- device scratch (no allocs) ----------------------
// fp32 (exact adds / elementwise)
__device__ __align__(16) float g_Pobs[BTv * HIDv];
__device__ __align__(16) float g_pre [BTv * HIDv];
__device__ __align__(16) float g_gi  [Bv * 3 * DETv];
__device__ __align__(16) float g_gh  [2 * Bv * 3 * DETv];
__device__ __align__(16) float g_p4  [4 * Bv * HIDv];
__device__ __align__(16) float g_p5  [4 * Bv * 2 * STOv];
__device__ __align__(16) float g_zero[DETv];              // zeros (fp32)
// packed fp16 activations (mma-A fragment layout)
__device__ __align__(16) __half g_obsP[BTv * Ev];         // [mb128][kb64][2048]
__device__ __align__(16) __half g_actP[BTv * Av];         // [mb128][kb4][2048]
__device__ __align__(16) __half g_hrP [(size_t)Tv * 2 * 128 * 2048]; // [t][mb2][kb128][2048]
__device__ __align__(16) __half g_rfP [(size_t)Tv * 2 * 64 * 2048];  // [t][mb2][kb64][2048]
__device__ __align__(16) __half g_rnnP[2 * 64 * 2048];
__device__ __align__(16) __half g_pfP [2 * 64 * 2048];
__device__ __align__(16) __half g_zrP [2 * 16 * 2048];
__device__ __align__(16) __half g_zeroH[131072];          // zeros (half)
// packed fp16 weights (mma-B fragment layout, swizzled)
__device__ __align__(16) __half g_WrnnP   [16 * 20 * 1024];
__device__ __align__(16) __half g_WihP    [96 * 64 * 1024];
__device__ __align__(16) __half g_WhhP    [(size_t)96 * 128 * 1024];
__device__ __align__(16) __half g_WpostP  [16 * 192 * 1024];
__device__ __align__(16) __half g_WpostmsP[8 * 64 * 1024];
__device__ __align__(16) __half g_WpriorP [16 * 128 * 1024];
__device__ __align__(16) __half g_WpriormsP[8 * 64 * 1024];
__device__ unsigned g_barcnt;
__device__ unsigned g_bargen;

// ------------------------------- helpers -----------------------------------
__device__ __forceinline__ float softplusf(float x) {
    return (x > 20.f) ? x : log1pf(expf(x));
}
__device__ __forceinline__ float sigmoidf(float x) {
    return 1.f / (1.f + expf(-x));
}
__device__ __forceinline__ uint32_t smem_u32(const void* p) {
    uint32_t a;
    asm("{ .reg .u64 t; cvta.to.shared.u64 t, %1; cvt.u32.u64 %0, t; }"
        : "=r"(a) : "l"(p));
    return a;
}
__device__ __forceinline__ void cpa16(uint32_t dst, const void* src) {
    size_t g = __cvta_generic_to_global(src);
    asm volatile("cp.async.cg.shared.global [%0], [%1], 16;"
                 :: "r"(dst), "l"(g) : "memory");
}
__device__ __forceinline__ void cpa_commit() {
    asm volatile("cp.async.commit_group;" ::: "memory");
}
__device__ __forceinline__ void mma16(float c[4], const uint32_t a[4],
                                      uint32_t b0, uint32_t b1) {
    asm volatile(
        "mma.sync.aligned.m16n8k16.row.col.f32.f16.f16.f32 "
        "{%0,%1,%2,%3},{%4,%5,%6,%7},{%8,%9},{%0,%1,%2,%3};\n"
        : "+f"(c[0]), "+f"(c[1]), "+f"(c[2]), "+f"(c[3])
        : "r"(a[0]), "r"(a[1]), "r"(a[2]), "r"(a[3]), "r"(b0), "r"(b1));
}
#define LDS128(r0, r1, r2, r3, addr) \
    asm volatile("ld.shared.v4.b32 {%0,%1,%2,%3}, [%4];" \
                 : "=r"(r0), "=r"(r1), "=r"(r2), "=r"(r3) : "r"(addr))

// packed-A index (halves) for (m, k even); pair (k, k+1) contiguous
__device__ __forceinline__ int apack(int m, int k, int mbStr) {
    int mb = m >> 7, m1 = m & 127;
    int wm = m1 >> 5, r = m1 & 31;
    int mf = (r >> 4) & 1, p8 = (r >> 3) & 1, g = r & 7;
    int kb = k >> 4, k1 = k & 15;
    int kk8 = k1 >> 3, tig = (k1 >> 1) & 3;
    int lane = g * 4 + tig;
    return mb * mbStr + kb * 2048 + ((wm * 2 + mf) * 32 + lane) * 8 + (p8 + 2 * kk8) * 2;
}

// ---------------------------- grid-wide barrier -----------------------------
__device__ __forceinline__ void gridbar(int nb) {
    __syncthreads();
    if (threadIdx.x == 0) {
        __threadfence();
        unsigned gen;
        asm volatile("ld.acquire.gpu.u32 %0, [%1];" : "=r"(gen) : "l"(&g_bargen) : "memory");
        unsigned arr = atomicAdd(&g_barcnt, 1u);
        if (arr == (unsigned)nb - 1u) {
            atomicExch(&g_barcnt, 0u);
            __threadfence();
            atomicAdd(&g_bargen, 1u);
        } else {
            unsigned cur;
            do {
                asm volatile("ld.acquire.gpu.u32 %0, [%1];" : "=r"(cur) : "l"(&g_bargen) : "memory");
            } while (cur == gen);
        }
        __threadfence();
    }
    __syncthreads();
}

// ------------------------------- GEMM core ----------------------------------
// acc[128x64] += A_packed x B_packed.  K multiple of 32.
// A layout: [mb][kb16][2048] fragment-packed. B: [nb][kb16][1024] packed+swizzled.
__device__ void gemm_h(uint32_t sa_u, uint32_t sb_u,
                       const __half* __restrict__ A, int mbStrA,
                       const __half* __restrict__ B, int nbStrB,
                       int K, int mb, int nb, float acc[2][4][4]) {
    const int tid = threadIdx.x;
    const __half* AP = A + (size_t)mb * mbStrA + tid * 8;
    const __half* BP = B + (size_t)nb * nbStrB + tid * 8;

#pragma unroll
    for (int i = 0; i < 2; i++)
#pragma unroll
        for (int j = 0; j < 4; j++)
#pragma unroll
            for (int c = 0; c < 4; c++) acc[i][j][c] = 0.f;

    auto load_stage = [&](int s, int kt) {
        cpa16(sa_u + s * 8192 + tid * 16, AP + (size_t)kt * 4096);
        cpa16(sa_u + s * 8192 + 4096 + tid * 16, AP + (size_t)kt * 4096 + 2048);
        cpa16(sb_u + s * 4096 + tid * 16, BP + (size_t)kt * 2048);
        cpa_commit();
    };

    const int nk = K >> 5;
#pragma unroll
    for (int s = 0; s < NSTAGE - 1; s++) {
        if (s < nk) load_stage(s, s);
        else cpa_commit();
    }

    const int lane = tid & 31, w = tid >> 5;
    const int wm = w >> 1, wn = w & 1;
    uint32_t aoff0 = (uint32_t)(((wm * 2 + 0) * 32 + lane) * 16);
    uint32_t aoff1 = (uint32_t)(((wm * 2 + 1) * 32 + lane) * 16);
    uint32_t blog = (uint32_t)((wn * 32 + lane) * 32);
    uint32_t bph0 = blog ^ (((blog >> 7) & 1u) << 4);

    for (int kt = 0; kt < nk; kt++) {
        asm volatile("cp.async.wait_group %0;" :: "n"(NSTAGE - 2) : "memory");
        __syncthreads();
        if (kt + NSTAGE - 1 < nk) load_stage((kt + NSTAGE - 1) & (NSTAGE - 1), kt + NSTAGE - 1);
        else cpa_commit();
        uint32_t sA = sa_u + (kt & (NSTAGE - 1)) * 8192;
        uint32_t sB = sb_u + (kt & (NSTAGE - 1)) * 4096;
#pragma unroll
        for (int x = 0; x < 2; x++) {
            uint32_t aR[2][4], bR[8];
            LDS128(aR[0][0], aR[0][1], aR[0][2], aR[0][3], sA + x * 4096 + aoff0);
            LDS128(aR[1][0], aR[1][1], aR[1][2], aR[1][3], sA + x * 4096 + aoff1);
            LDS128(bR[0], bR[1], bR[2], bR[3], sB + x * 2048 + bph0);
            LDS128(bR[4], bR[5], bR[6], bR[7], sB + x * 2048 + (bph0 ^ 16u));
#pragma unroll
            for (int mf = 0; mf < 2; mf++)
#pragma unroll
                for (int nf = 0; nf < 4; nf++)
                    mma16(acc[mf][nf], aR[mf], bR[nf * 2], bR[nf * 2 + 1]);
        }
    }
    __syncthreads();
}

// epilogue: per (row, even col) pair
template <typename F>
__device__ __forceinline__ void epi2(int bm0, int bn0, float acc[2][4][4], F&& f) {
    const int tid = threadIdx.x;
    const int lane = tid & 31, w = tid >> 5;
    const int wm = w >> 1, wn = w & 1;
    const int g = lane >> 2, tig = lane & 3;
#pragma unroll
    for (int mf = 0; mf < 2; mf++)
#pragma unroll
        for (int nf = 0; nf < 4; nf++)
#pragma unroll
            for (int h = 0; h < 2; h++) {
                int row = bm0 + wm * 32 + mf * 16 + g + h * 8;
                int col = bn0 + wn * 32 + nf * 8 + tig * 2;
                f(row, col, acc[mf][nf][h * 2], acc[mf][nf][h * 2 + 1]);
            }
}

// ---------------------------- pack kernels ----------------------------------
// B pack: one 64n x 16k block per CTA -> 1024 halves (fragment order + swizzle)
__global__ __launch_bounds__(256)
void packB_k(const float* __restrict__ Wrnn, const float* __restrict__ Wih,
             const float* __restrict__ Whh, const float* __restrict__ Wpost,
             const float* __restrict__ Wpostms, const float* __restrict__ Wprior,
             const float* __restrict__ Wpriorms) {
    int b = blockIdx.x;
    const float* src; __half* dst; int N, K; bool KN;
    if (b < 320)        { src = Wrnn;     dst = g_WrnnP;     N = 1024; K = 320;  KN = true;  }
    else if (b < 6464)  { b -= 320;  src = Wih;     dst = g_WihP;     N = 6144; K = 1024; KN = false; }
    else if (b < 18752) { b -= 6464; src = Whh;     dst = g_WhhP;     N = 6144; K = 2048; KN = false; }
    else if (b < 21824) { b -= 18752; src = Wpost;  dst = g_WpostP;   N = 1024; K = 3072; KN = true;  }
    else if (b < 22336) { b -= 21824; src = Wpostms; dst = g_WpostmsP; N = 512; K = 1024; KN = true;  }
    else if (b < 24384) { b -= 22336; src = Wprior; dst = g_WpriorP;  N = 1024; K = 2048; KN = true;  }
    else                { b -= 24384; src = Wpriorms; dst = g_WpriormsP; N = 512; K = 1024; KN = true; }
    int nkb = K >> 4;
    int nb = b / nkb, kb = b % nkb;
    int tid = threadIdx.x;
    int nf = tid & 3, wl = tid >> 2;
    int lane = wl & 31, wn = wl >> 5;
    int g = lane >> 2, tig = lane & 3;
    int n = nb * 64 + wn * 32 + nf * 8 + g;
    uint32_t swz = (((uint32_t)(tid * 8) >> 7) & 1u) << 4;
    char* blk = (char*)(dst + (size_t)blockIdx.x * 0);  // silence unused warn pattern
    blk = (char*)dst + (size_t)b * 2048;
#pragma unroll
    for (int reg = 0; reg < 2; reg++) {
        int k = kb * 16 + reg * 8 + tig * 2;
        float v0 = KN ? src[(size_t)k * N + n] : src[(size_t)n * K + k];
        float v1 = KN ? src[(size_t)(k + 1) * N + n] : src[(size_t)n * K + k + 1];
        uint32_t phys = (uint32_t)(tid * 8 + reg * 4) ^ swz;
        *(__half2*)(blk + phys) = __floats2half2_rn(v0, v1);
    }
}

// A pack: obs (8192 blocks) + prev-actions (512 blocks)
__global__ __launch_bounds__(256)
void packA_k(const float* __restrict__ obs, const float* __restrict__ act) {
    int b = blockIdx.x;
    int tid = threadIdx.x;
    int lane = tid & 31, mfwm = tid >> 5;
    int mf = mfwm & 1, wm = mfwm >> 1;
    int g = lane >> 2, tig = lane & 3;
    if (b < 8192) {
        int mb = b >> 6, kb = b & 63;
        __half2* dst = (__half2*)(g_obsP + (size_t)b * 2048) + tid * 4;
#pragma unroll
        for (int r = 0; r < 4; r++) {
            int p8 = r & 1, kk8 = r >> 1;
            int m = mb * 128 + wm * 32 + mf * 16 + p8 * 8 + g;
            int k = kb * 16 + kk8 * 8 + tig * 2;
            float2 v = *(const float2*)&obs[(size_t)m * 1024 + k];
            dst[r] = __floats2half2_rn(v.x, v.y);
        }
    } else {
        b -= 8192;
        int mb = b >> 2, kb = b & 3;
        __half2* dst = (__half2*)(g_actP + (size_t)b * 2048) + tid * 4;
#pragma unroll
        for (int r = 0; r < 4; r++) {
            int p8 = r & 1, kk8 = r >> 1;
            int m = mb * 128 + wm * 32 + mf * 16 + p8 * 8 + g;
            int k = kb * 16 + kk8 * 8 + tig * 2;
            int t = m & 63;
            float2 v = make_float2(0.f, 0.f);
            if (t) v = *(const float2*)&act[(size_t)(m - 1) * 64 + k];
            dst[r] = __floats2half2_rn(v.x, v.y);
        }
    }
}

__global__ void dummy_k() {}

// --------------------------- batched pre / post -----------------------------
__global__ __launch_bounds__(256)
void prep_k(const float* __restrict__ bpost_in, const float* __restrict__ brnn) {
    extern __shared__ char dyn[];
    uint32_t sa_u = smem_u32(dyn), sb_u = sa_u + NSTAGE * 8192;
    float acc[2][4][4];
    int tile = blockIdx.x;
    if (tile < 2048) {   // Pobs
        int mb = tile & 127, nb = tile >> 7;
        gemm_h(sa_u, sb_u, g_obsP, 131072, g_WpostP + 131072, 196608, 1024, mb, nb, acc);
        epi2(mb << 7, nb << 6, acc, [&](int r, int c, float v0, float v1) {
            float2 o = make_float2(v0 + bpost_in[c], v1 + bpost_in[c + 1]);
            *(float2*)&g_Pobs[(size_t)r * HIDv + c] = o;
        });
    } else {             // pre
        tile -= 2048;
        int mb = tile & 127, nb = tile >> 7;
        gemm_h(sa_u, sb_u, g_actP, 8192, g_WrnnP + 16384, 20480, 64, mb, nb, acc);
        epi2(mb << 7, nb << 6, acc, [&](int r, int c, float v0, float v1) {
            float2 o = make_float2(v0 + brnn[c], v1 + brnn[c + 1]);
            *(float2*)&g_pre[(size_t)r * HIDv + c] = o;
        });
    }
}

__global__ __launch_bounds__(256)
void rf_k(const float* __restrict__ bprior_in) {
    extern __shared__ char dyn[];
    uint32_t sa_u = smem_u32(dyn), sb_u = sa_u + NSTAGE * 8192;
    float acc[2][4][4];
    int tile = blockIdx.x;           // 2048
    int low = tile & 127, t = low >> 1, mb = low & 1, nb = tile >> 7;
    gemm_h(sa_u, sb_u, g_hrP + (size_t)t * 524288, 262144, g_WpriorP, 131072,
           2048, mb, nb, acc);
    __half* out = g_rfP + (size_t)t * 262144;
    epi2(mb << 7, nb << 6, acc, [&](int r, int c, float v0, float v1) {
        v0 = fmaxf(v0 + bprior_in[c], 0.f);
        v1 = fmaxf(v1 + bprior_in[c + 1], 0.f);
        *(__half2*)&out[apack(r, c, 131072)] = __floats2half2_rn(v0, v1);
    });
}

__global__ __launch_bounds__(256)
void ms_k(const float* __restrict__ bprior_ms,
          float* __restrict__ qm_o, float* __restrict__ qs_o) {
    extern __shared__ char dyn[];
    uint32_t sa_u = smem_u32(dyn), sb_u = sa_u + NSTAGE * 8192;
    float acc[2][4][4];
    int tile = blockIdx.x;           // 1024
    int low = tile & 127, t = low >> 1, mb = low & 1, nb = tile >> 7;
    gemm_h(sa_u, sb_u, g_rfP + (size_t)t * 262144, 131072, g_WpriormsP, 65536,
           1024, mb, nb, acc);
    int bn0 = nb << 6;
    if (bn0 < STOv) {
        epi2(mb << 7, bn0, acc, [&](int r, int c, float v0, float v1) {
            size_t o = ((size_t)r * Tv + t) * STOv + c;
            *(float2*)&qm_o[o] = make_float2(v0 + bprior_ms[c], v1 + bprior_ms[c + 1]);
        });
    } else {
        epi2(mb << 7, bn0, acc, [&](int r, int c, float v0, float v1) {
            size_t o = ((size_t)r * Tv + t) * STOv + (c - STOv);
            *(float2*)&qs_o[o] = make_float2(softplusf(v0 + bprior_ms[c]) + 0.1f,
                                             softplusf(v1 + bprior_ms[c + 1]) + 0.1f);
        });
    }
}

// --------------------------- persistent scan kernel -------------------------
struct ScanArgs {
    const float* noise;
    const float* bih; const float* bhh;
    const float* bpost_ms;
    float* h_o; float* z_o; float* pm_o; float* ps_o;
    int nb;
};

__global__ __launch_bounds__(256)
void scan_k(ScanArgs a) {
    extern __shared__ char dyn[];
    uint32_t sa_u = smem_u32(dyn), sb_u = sa_u + NSTAGE * 8192;
    const int nb = a.nb;
    float acc[2][4][4];
    const size_t GHS = (size_t)Bv * 3 * DETv;

    for (int t = 0; t < Tv; t++) {
        // ---- P1: rnn = relu(z_prev @ Wz + pre_t)   32 tiles, K=256
        {
            const __half* Az = t ? g_zrP : g_zeroH;
            int mstr = t ? 32768 : 0;
            for (int tile = blockIdx.x; tile < 32; tile += nb) {
                int mb = tile & 1, nbt = tile >> 1;
                gemm_h(sa_u, sb_u, Az, mstr, g_WrnnP, 20480, 256, mb, nbt, acc);
                epi2(mb << 7, nbt << 6, acc, [&](int r, int c, float v0, float v1) {
                    float2 p = *(const float2*)&g_pre[((size_t)r * Tv + t) * HIDv + c];
                    v0 = fmaxf(v0 + p.x, 0.f);
                    v1 = fmaxf(v1 + p.y, 0.f);
                    *(__half2*)&g_rnnP[apack(r, c, 131072)] = __floats2half2_rn(v0, v1);
                });
            }
        }
        gridbar(nb);

        // ---- P2: 576 uniform K=1024 tiles (gi 192 + gh 2x192)
        {
            for (int tile = blockIdx.x; tile < 576; tile += nb) {
                if (tile < 192) {
                    int mb = tile & 1, nbt = tile >> 1;
                    gemm_h(sa_u, sb_u, g_rnnP, 131072, g_WihP, 65536, 1024, mb, nbt, acc);
                    epi2(mb << 7, nbt << 6, acc, [&](int r, int c, float v0, float v1) {
                        *(float2*)&g_gi[(size_t)r * (3 * DETv) + c] =
                            make_float2(v0 + a.bih[c], v1 + a.bih[c + 1]);
                    });
                } else {
                    int u = tile - 192, kh = u / 192, v2 = u % 192;
                    int mb = v2 & 1, nbt = v2 >> 1;
                    const __half* Ah = t ? g_hrP + (size_t)(t - 1) * 524288 + kh * 131072
                                         : g_zeroH;
                    int mstr = t ? 262144 : 0;
                    float* outp = g_gh + (size_t)kh * GHS;
                    gemm_h(sa_u, sb_u, Ah, mstr, g_WhhP + (size_t)kh * 65536, 131072,
                           1024, mb, nbt, acc);
                    epi2(mb << 7, nbt << 6, acc, [&](int r, int c, float v0, float v1) {
                        *(float2*)&outp[(size_t)r * (3 * DETv) + c] = make_float2(v0, v1);
                    });
                }
            }
        }
        gridbar(nb);

        // ---- P3: GRU (gh reduce fused) -> h_t fp32 + g_hrP half
        {
            const float* hp = t ? a.h_o + (size_t)(t - 1) * DETv : g_zero;
            size_t hps = t ? (size_t)Tv * DETv : 0;
            __half* hrp = g_hrP + (size_t)t * 524288;
            for (int idx = blockIdx.x * 256 + threadIdx.x; idx < Bv * DETv / 2;
                 idx += nb * 256) {
                int m = idx >> 10, j = (idx & 1023) * 2;
                size_t base = (size_t)m * (3 * DETv) + j;
                float2 gi0 = *(const float2*)&g_gi[base];
                float2 gi1 = *(const float2*)&g_gi[base + DETv];
                float2 gi2 = *(const float2*)&g_gi[base + 2 * DETv];
                float2 ga0 = *(const float2*)&g_gh[base];
                float2 ga1 = *(const float2*)&g_gh[base + DETv];
                float2 ga2 = *(const float2*)&g_gh[base + 2 * DETv];
                float2 gb0 = *(const float2*)&g_gh[GHS + base];
                float2 gb1 = *(const float2*)&g_gh[GHS + base + DETv];
                float2 gb2 = *(const float2*)&g_gh[GHS + base + 2 * DETv];
                float2 bh0 = *(const float2*)&a.bhh[j];
                float2 bh1 = *(const float2*)&a.bhh[DETv + j];
                float2 bh2 = *(const float2*)&a.bhh[2 * DETv + j];
                float2 hpv = *(const float2*)&hp[(size_t)m * hps + j];
                float r0 = sigmoidf(gi0.x + ga0.x + gb0.x + bh0.x);
                float r1 = sigmoidf(gi0.y + ga0.y + gb0.y + bh0.y);
                float u0 = sigmoidf(gi1.x + ga1.x + gb1.x + bh1.x);
                float u1 = sigmoidf(gi1.y + ga1.y + gb1.y + bh1.y);
                float n0 = tanhf(gi2.x + r0 * (ga2.x + gb2.x + bh2.x));
                float n1 = tanhf(gi2.y + r1 * (ga2.y + gb2.y + bh2.y));
                float h0 = (1.f - u0) * n0 + u0 * hpv.x;
                float h1 = (1.f - u1) * n1 + u1 * hpv.y;
                *(float2*)&a.h_o[((size_t)m * Tv + t) * DETv + j] = make_float2(h0, h1);
                *(__half2*)&hrp[apack(m, j, 262144)] = __floats2half2_rn(h0, h1);
            }
        }
        gridbar(nb);

        // ---- P4a: pf split-K partials (128 tiles: 4ks x 32, K=512)
        for (int tile = blockIdx.x; tile < 128; tile += nb) {
            int ks = tile >> 5, rem = tile & 31;
            int mb = rem & 1, nbt = rem >> 1;
            gemm_h(sa_u, sb_u, g_hrP + (size_t)t * 524288 + ks * 65536, 262144,
                   g_WpostP + ks * 32768, 196608, 512, mb, nbt, acc);
            float* outp = g_p4 + (size_t)ks * Bv * HIDv;
            epi2(mb << 7, nbt << 6, acc, [&](int r, int c, float v0, float v1) {
                *(float2*)&outp[(size_t)r * HIDv + c] = make_float2(v0, v1);
            });
        }
        gridbar(nb);

        // ---- P4b: reduce + Pobs + relu -> g_pfP
        for (int idx = blockIdx.x * 256 + threadIdx.x; idx < Bv * HIDv / 2;
             idx += nb * 256) {
            int m = idx >> 9, j = (idx & 511) * 2;
            size_t i2 = (size_t)m * HIDv + j;
            const size_t S = (size_t)Bv * HIDv;
            float2 s0 = *(const float2*)&g_p4[i2];
            float2 s1 = *(const float2*)&g_p4[S + i2];
            float2 s2 = *(const float2*)&g_p4[2 * S + i2];
            float2 s3 = *(const float2*)&g_p4[3 * S + i2];
            float2 po = *(const float2*)&g_Pobs[((size_t)m * Tv + t) * HIDv + j];
            float v0 = fmaxf(s0.x + s1.x + s2.x + s3.x + po.x, 0.f);
            float v1 = fmaxf(s0.y + s1.y + s2.y + s3.y + po.y, 0.f);
            *(__half2*)&g_pfP[apack(m, j, 131072)] = __floats2half2_rn(v0, v1);
        }
        gridbar(nb);

        // ---- P5a: [pm|ps] split-K partials (64 tiles: 4ks x 16, K=256)
        for (int tile = blockIdx.x; tile < 64; tile += nb) {
            int ks = tile >> 4, rem = tile & 15;
            int mb = rem & 1, nbt = rem >> 1;
            gemm_h(sa_u, sb_u, g_pfP + ks * 32768, 131072,
                   g_WpostmsP + ks * 16384, 65536, 256, mb, nbt, acc);
            float* outp = g_p5 + (size_t)ks * Bv * 2 * STOv;
            epi2(mb << 7, nbt << 6, acc, [&](int r, int c, float v0, float v1) {
                *(float2*)&outp[(size_t)r * (2 * STOv) + c] = make_float2(v0, v1);
            });
        }
        gridbar(nb);

        // ---- P5b: pm, ps, z + g_zrP
        for (int idx = blockIdx.x * 256 + threadIdx.x; idx < Bv * STOv / 2;
             idx += nb * 256) {
            int m = idx >> 7, j = (idx & 127) * 2;
            size_t b0 = (size_t)m * (2 * STOv);
            const size_t S = (size_t)Bv * (2 * STOv);
            float2 pmv = make_float2(a.bpost_ms[j], a.bpost_ms[j + 1]);
            float2 srv = make_float2(a.bpost_ms[STOv + j], a.bpost_ms[STOv + j + 1]);
#pragma unroll
            for (int ks = 0; ks < 4; ks++) {
                float2 x0 = *(const float2*)&g_p5[ks * S + b0 + j];
                float2 x1 = *(const float2*)&g_p5[ks * S + b0 + STOv + j];
                pmv.x += x0.x; pmv.y += x0.y;
                srv.x += x1.x; srv.y += x1.y;
            }
            float ps0 = softplusf(srv.x) + 0.1f;
            float ps1 = softplusf(srv.y) + 0.1f;
            size_t o = ((size_t)m * Tv + t) * STOv + j;
            float2 nz = *(const float2*)&a.noise[o];
            float z0 = pmv.x + ps0 * nz.x;
            float z1 = pmv.y + ps1 * nz.y;
            *(float2*)&a.pm_o[o] = pmv;
            *(float2*)&a.ps_o[o] = make_float2(ps0, ps1);
            *(float2*)&a.z_o[o] = make_float2(z0, z1);
            *(__half2*)&g_zrP[apack(m, j, 32768)] = __floats2half2_rn(z0, z1);
        }
        gridbar(nb);
    }
}

// ------------------------------- launch -------------------------------------
extern "C" void kernel_launch(void* const* d_in, const int* in_sizes, int n_in,
                              void* d_out, int out_size) {
    const float* obs      = (const float*)d_in[0];
    const float* act      = (const float*)d_in[1];
    const float* noise    = (const float*)d_in[4];
    const float* Wrnn     = (const float*)d_in[5];
    const float* brnn     = (const float*)d_in[6];
    const float* Wih      = (const float*)d_in[7];
    const float* Whh      = (const float*)d_in[8];
    const float* bih      = (const float*)d_in[9];
    const float* bhh      = (const float*)d_in[10];
    const float* Wpost_in = (const float*)d_in[11];
    const float* bpost_in = (const float*)d_in[12];
    const float* Wpost_ms = (const float*)d_in[13];
    const float* bpost_ms = (const float*)d_in[14];
    const float* Wprior_in= (const float*)d_in[15];
    const float* bprior_in= (const float*)d_in[16];
    const float* Wprior_ms= (const float*)d_in[17];
    const float* bprior_ms= (const float*)d_in[18];

    float* out  = (float*)d_out;
    float* h_o  = out;
    float* z_o  = h_o + (size_t)BTv * DETv;
    float* pm_o = z_o + (size_t)BTv * STOv;
    float* ps_o = pm_o + (size_t)BTv * STOv;
    float* qm_o = ps_o + (size_t)BTv * STOv;
    float* qs_o = qm_o + (size_t)BTv * STOv;

    cudaFuncSetAttribute(prep_k, cudaFuncAttributeMaxDynamicSharedMemorySize, DYN_SMEM);
    cudaFuncSetAttribute(rf_k,   cudaFuncAttributeMaxDynamicSharedMemorySize, DYN_SMEM);
    cudaFuncSetAttribute(ms_k,   cudaFuncAttributeMaxDynamicSharedMemorySize, DYN_SMEM);
    cudaFuncSetAttribute(scan_k, cudaFuncAttributeMaxDynamicSharedMemorySize, DYN_SMEM);

    // launches: 1 packB, 2 packA, 3 prep, 4-5 dummies, 6 scan, 7 rf, 8 ms
    packB_k<<<24896, 256>>>(Wrnn, Wih, Whh, Wpost_in, Wpost_ms, Wprior_in, Wprior_ms);
    packA_k<<<8704, 256>>>(obs, act);
    prep_k<<<4096, 256, DYN_SMEM>>>(bpost_in, brnn);
    dummy_k<<<1, 32>>>();
    dummy_k<<<1, 32>>>();

    int nsm = 0, maxb = 0;
    cudaDeviceGetAttribute(&nsm, cudaDevAttrMultiProcessorCount, 0);
    if (nsm <= 0) nsm = 148;
    cudaOccupancyMaxActiveBlocksPerMultiprocessor(&maxb, scan_k, 256, DYN_SMEM);
    if (maxb > 2) maxb = 2;
    if (maxb < 1) maxb = 1;
    int nb = nsm * maxb;

    ScanArgs a;
    a.noise = noise;
    a.bih = bih; a.bhh = bhh;
    a.bpost_ms = bpost_ms;
    a.h_o = h_o; a.z_o = z_o; a.pm_o = pm_o; a.ps_o = ps_o;
    a.nb = nb;
    scan_k<<<nb, 256, DYN_SMEM>>>(a);

    rf_k<<<2048, 256, DYN_SMEM>>>(bprior_in);
    ms_k<<<1024, 256, DYN_SMEM>>>(bprior_ms, qm_o, qs_o);
}

// round 13
// speedup vs baseline: 3.6426x; 1.0190x over previous
#include <cuda_runtime.h>
#include <cuda_fp16.h>
#include <cstdint>
#include <cstddef>

// ---------------------------------------------------------------------------
// RSSM scan: B=256, T=64, A=64, E=1024, HID=1024, DET=2048, STO=256
// fp16 m16n8k16 mma, fragment-packed operands, 4-stage cp.async, persistent scan.
// ---------------------------------------------------------------------------

#define Bv   256
#define Tv   64
#define BTv  (Bv*Tv)          // 16384
#define Av   64
#define Ev   1024
#define HIDv 1024
#define DETv 2048
#define STOv 256

#define BM 128
#define BN 64
#define NSTAGE 4
// smem: A stages 4*8KB + B stages 4*4KB
#define DYN_SMEM 49152

// ------------------------- device scratch (no allocs) ----------------------
// fp32 (exact adds / elementwise)
__device__ __align__(16) float g_Pobs[BTv * HIDv];
__device__ __align__(16) float g_pre [BTv * HIDv];
__device__ __align__(16) float g_gi  [Bv * 3 * DETv];
__device__ __align__(16) float g_gh  [2 * Bv * 3 * DETv];
__device__ __align__(16) float g_p4  [4 * Bv * HIDv];
__device__ __align__(16) float g_p5  [4 * Bv * 2 * STOv];
__device__ __align__(16) float g_zero[DETv];              // zeros (fp32)
// packed fp16 activations (mma-A fragment layout)
__device__ __align__(16) __half g_obsP[BTv * Ev];         // [mb128][kb64][2048]
__device__ __align__(16) __half g_actP[BTv * Av];         // [mb128][kb4][2048]
__device__ __align__(16) __half g_hrP [(size_t)Tv * 2 * 128 * 2048]; // [t][mb2][kb128][2048]
__device__ __align__(16) __half g_rfP [(size_t)Tv * 2 * 64 * 2048];  // [t][mb2][kb64][2048]
__device__ __align__(16) __half g_rnnP[2 * 64 * 2048];
__device__ __align__(16) __half g_pfP [2 * 64 * 2048];
__device__ __align__(16) __half g_zrP [2 * 16 * 2048];
__device__ __align__(16) __half g_zeroH[131072];          // zeros (half)
// packed fp16 weights (mma-B fragment layout, swizzled)
__device__ __align__(16) __half g_WrnnP   [16 * 20 * 1024];
__device__ __align__(16) __half g_WihP    [96 * 64 * 1024];
__device__ __align__(16) __half g_WhhP    [(size_t)96 * 128 * 1024];
__device__ __align__(16) __half g_WpostP  [16 * 192 * 1024];
__device__ __align__(16) __half g_WpostmsP[8 * 64 * 1024];
__device__ __align__(16) __half g_WpriorP [16 * 128 * 1024];
__device__ __align__(16) __half g_WpriormsP[8 * 64 * 1024];
__device__ unsigned g_barcnt;
__device__ unsigned g_bargen;

// ------------------------------- helpers -----------------------------------
__device__ __forceinline__ float softplusf(float x) {
    return (x > 20.f) ? x : log1pf(expf(x));
}
__device__ __forceinline__ float sigmoidf(float x) {
    return 1.f / (1.f + expf(-x));
}
__device__ __forceinline__ uint32_t smem_u32(const void* p) {
    uint32_t a;
    asm("{ .reg .u64 t; cvta.to.shared.u64 t, %1; cvt.u32.u64 %0, t; }"
        : "=r"(a) : "l"(p));
    return a;
}
__device__ __forceinline__ void cpa16(uint32_t dst, const void* src) {
    size_t g = __cvta_generic_to_global(src);
    asm volatile("cp.async.cg.shared.global [%0], [%1], 16;"
                 :: "r"(dst), "l"(g) : "memory");
}
__device__ __forceinline__ void cpa_commit() {
    asm volatile("cp.async.commit_group;" ::: "memory");
}
__device__ __forceinline__ void mma16(float c[4], const uint32_t a[4],
                                      uint32_t b0, uint32_t b1) {
    asm volatile(
        "mma.sync.aligned.m16n8k16.row.col.f32.f16.f16.f32 "
        "{%0,%1,%2,%3},{%4,%5,%6,%7},{%8,%9},{%0,%1,%2,%3};\n"
        : "+f"(c[0]), "+f"(c[1]), "+f"(c[2]), "+f"(c[3])
        : "r"(a[0]), "r"(a[1]), "r"(a[2]), "r"(a[3]), "r"(b0), "r"(b1));
}
#define LDS128(r0, r1, r2, r3, addr) \
    asm volatile("ld.shared.v4.b32 {%0,%1,%2,%3}, [%4];" \
                 : "=r"(r0), "=r"(r1), "=r"(r2), "=r"(r3) : "r"(addr))

// packed-A index (halves) for (m, k even); pair (k, k+1) contiguous
__device__ __forceinline__ int apack(int m, int k, int mbStr) {
    int mb = m >> 7, m1 = m & 127;
    int wm = m1 >> 5, r = m1 & 31;
    int mf = (r >> 4) & 1, p8 = (r >> 3) & 1, g = r & 7;
    int kb = k >> 4, k1 = k & 15;
    int kk8 = k1 >> 3, tig = (k1 >> 1) & 3;
    int lane = g * 4 + tig;
    return mb * mbStr + kb * 2048 + ((wm * 2 + mf) * 32 + lane) * 8 + (p8 + 2 * kk8) * 2;
}

// ---------------------------- grid-wide barrier -----------------------------
__device__ __forceinline__ void gridbar(int nb) {
    __syncthreads();
    if (threadIdx.x == 0) {
        __threadfence();
        unsigned gen;
        asm volatile("ld.acquire.gpu.u32 %0, [%1];" : "=r"(gen) : "l"(&g_bargen) : "memory");
        unsigned arr = atomicAdd(&g_barcnt, 1u);
        if (arr == (unsigned)nb - 1u) {
            atomicExch(&g_barcnt, 0u);
            __threadfence();
            atomicAdd(&g_bargen, 1u);
        } else {
            unsigned cur;
            do {
                asm volatile("ld.acquire.gpu.u32 %0, [%1];" : "=r"(cur) : "l"(&g_bargen) : "memory");
            } while (cur == gen);
        }
        __threadfence();
    }
    __syncthreads();
}

// ------------------------------- GEMM core ----------------------------------
// acc[128x64] += A_packed x B_packed.  K multiple of 32.
// A layout: [mb][kb16][2048] fragment-packed. B: [nb][kb16][1024] packed+swizzled.
__device__ void gemm_h(uint32_t sa_u, uint32_t sb_u,
                       const __half* __restrict__ A, int mbStrA,
                       const __half* __restrict__ B, int nbStrB,
                       int K, int mb, int nb, float acc[2][4][4]) {
    const int tid = threadIdx.x;
    const __half* AP = A + (size_t)mb * mbStrA + tid * 8;
    const __half* BP = B + (size_t)nb * nbStrB + tid * 8;

#pragma unroll
    for (int i = 0; i < 2; i++)
#pragma unroll
        for (int j = 0; j < 4; j++)
#pragma unroll
            for (int c = 0; c < 4; c++) acc[i][j][c] = 0.f;

    auto load_stage = [&](int s, int kt) {
        cpa16(sa_u + s * 8192 + tid * 16, AP + (size_t)kt * 4096);
        cpa16(sa_u + s * 8192 + 4096 + tid * 16, AP + (size_t)kt * 4096 + 2048);
        cpa16(sb_u + s * 4096 + tid * 16, BP + (size_t)kt * 2048);
        cpa_commit();
    };

    const int nk = K >> 5;
#pragma unroll
    for (int s = 0; s < NSTAGE - 1; s++) {
        if (s < nk) load_stage(s, s);
        else cpa_commit();
    }

    const int lane = tid & 31, w = tid >> 5;
    const int wm = w >> 1, wn = w & 1;
    uint32_t aoff0 = (uint32_t)(((wm * 2 + 0) * 32 + lane) * 16);
    uint32_t aoff1 = (uint32_t)(((wm * 2 + 1) * 32 + lane) * 16);
    uint32_t blog = (uint32_t)((wn * 32 + lane) * 32);
    uint32_t bph0 = blog ^ (((blog >> 7) & 1u) << 4);

    for (int kt = 0; kt < nk; kt++) {
        asm volatile("cp.async.wait_group %0;" :: "n"(NSTAGE - 2) : "memory");
        __syncthreads();
        if (kt + NSTAGE - 1 < nk) load_stage((kt + NSTAGE - 1) & (NSTAGE - 1), kt + NSTAGE - 1);
        else cpa_commit();
        uint32_t sA = sa_u + (kt & (NSTAGE - 1)) * 8192;
        uint32_t sB = sb_u + (kt & (NSTAGE - 1)) * 4096;
#pragma unroll
        for (int x = 0; x < 2; x++) {
            uint32_t aR[2][4], bR[8];
            LDS128(aR[0][0], aR[0][1], aR[0][2], aR[0][3], sA + x * 4096 + aoff0);
            LDS128(aR[1][0], aR[1][1], aR[1][2], aR[1][3], sA + x * 4096 + aoff1);
            LDS128(bR[0], bR[1], bR[2], bR[3], sB + x * 2048 + bph0);
            LDS128(bR[4], bR[5], bR[6], bR[7], sB + x * 2048 + (bph0 ^ 16u));
#pragma unroll
            for (int mf = 0; mf < 2; mf++)
#pragma unroll
                for (int nf = 0; nf < 4; nf++)
                    mma16(acc[mf][nf], aR[mf], bR[nf * 2], bR[nf * 2 + 1]);
        }
    }
    __syncthreads();
}

// epilogue: per (row, even col) pair
template <typename F>
__device__ __forceinline__ void epi2(int bm0, int bn0, float acc[2][4][4], F&& f) {
    const int tid = threadIdx.x;
    const int lane = tid & 31, w = tid >> 5;
    const int wm = w >> 1, wn = w & 1;
    const int g = lane >> 2, tig = lane & 3;
#pragma unroll
    for (int mf = 0; mf < 2; mf++)
#pragma unroll
        for (int nf = 0; nf < 4; nf++)
#pragma unroll
            for (int h = 0; h < 2; h++) {
                int row = bm0 + wm * 32 + mf * 16 + g + h * 8;
                int col = bn0 + wn * 32 + nf * 8 + tig * 2;
                f(row, col, acc[mf][nf][h * 2], acc[mf][nf][h * 2 + 1]);
            }
}

// ---------------------------- pack kernels ----------------------------------
// B pack: one 64n x 16k block per CTA -> 1024 halves (fragment order + swizzle)
__global__ __launch_bounds__(256)
void packB_k(const float* __restrict__ Wrnn, const float* __restrict__ Wih,
             const float* __restrict__ Whh, const float* __restrict__ Wpost,
             const float* __restrict__ Wpostms, const float* __restrict__ Wprior,
             const float* __restrict__ Wpriorms) {
    int b = blockIdx.x;
    const float* src; __half* dst; int N, K; bool KN;
    if (b < 320)        { src = Wrnn;     dst = g_WrnnP;     N = 1024; K = 320;  KN = true;  }
    else if (b < 6464)  { b -= 320;  src = Wih;     dst = g_WihP;     N = 6144; K = 1024; KN = false; }
    else if (b < 18752) { b -= 6464; src = Whh;     dst = g_WhhP;     N = 6144; K = 2048; KN = false; }
    else if (b < 21824) { b -= 18752; src = Wpost;  dst = g_WpostP;   N = 1024; K = 3072; KN = true;  }
    else if (b < 22336) { b -= 21824; src = Wpostms; dst = g_WpostmsP; N = 512; K = 1024; KN = true;  }
    else if (b < 24384) { b -= 22336; src = Wprior; dst = g_WpriorP;  N = 1024; K = 2048; KN = true;  }
    else                { b -= 24384; src = Wpriorms; dst = g_WpriormsP; N = 512; K = 1024; KN = true; }
    int nkb = K >> 4;
    int nb = b / nkb, kb = b % nkb;
    int tid = threadIdx.x;
    int nf = tid & 3, wl = tid >> 2;
    int lane = wl & 31, wn = wl >> 5;
    int g = lane >> 2, tig = lane & 3;
    int n = nb * 64 + wn * 32 + nf * 8 + g;
    uint32_t swz = (((uint32_t)(tid * 8) >> 7) & 1u) << 4;
    char* blk = (char*)dst + (size_t)b * 2048;
#pragma unroll
    for (int reg = 0; reg < 2; reg++) {
        int k = kb * 16 + reg * 8 + tig * 2;
        float v0 = KN ? src[(size_t)k * N + n] : src[(size_t)n * K + k];
        float v1 = KN ? src[(size_t)(k + 1) * N + n] : src[(size_t)n * K + k + 1];
        uint32_t phys = (uint32_t)(tid * 8 + reg * 4) ^ swz;
        *(__half2*)(blk + phys) = __floats2half2_rn(v0, v1);
    }
}

// A pack: obs (8192 blocks) + prev-actions (512 blocks)
__global__ __launch_bounds__(256)
void packA_k(const float* __restrict__ obs, const float* __restrict__ act) {
    int b = blockIdx.x;
    int tid = threadIdx.x;
    int lane = tid & 31, mfwm = tid >> 5;
    int mf = mfwm & 1, wm = mfwm >> 1;
    int g = lane >> 2, tig = lane & 3;
    if (b < 8192) {
        int mb = b >> 6, kb = b & 63;
        __half2* dst = (__half2*)(g_obsP + (size_t)b * 2048) + tid * 4;
#pragma unroll
        for (int r = 0; r < 4; r++) {
            int p8 = r & 1, kk8 = r >> 1;
            int m = mb * 128 + wm * 32 + mf * 16 + p8 * 8 + g;
            int k = kb * 16 + kk8 * 8 + tig * 2;
            float2 v = *(const float2*)&obs[(size_t)m * 1024 + k];
            dst[r] = __floats2half2_rn(v.x, v.y);
        }
    } else {
        b -= 8192;
        int mb = b >> 2, kb = b & 3;
        __half2* dst = (__half2*)(g_actP + (size_t)b * 2048) + tid * 4;
#pragma unroll
        for (int r = 0; r < 4; r++) {
            int p8 = r & 1, kk8 = r >> 1;
            int m = mb * 128 + wm * 32 + mf * 16 + p8 * 8 + g;
            int k = kb * 16 + kk8 * 8 + tig * 2;
            int t = m & 63;
            float2 v = make_float2(0.f, 0.f);
            if (t) v = *(const float2*)&act[(size_t)(m - 1) * 64 + k];
            dst[r] = __floats2half2_rn(v.x, v.y);
        }
    }
}

// --------------------------- batched pre / post -----------------------------
__global__ __launch_bounds__(256)
void prep_k(const float* __restrict__ bpost_in, const float* __restrict__ brnn) {
    extern __shared__ char dyn[];
    uint32_t sa_u = smem_u32(dyn), sb_u = sa_u + NSTAGE * 8192;
    float acc[2][4][4];
    int tile = blockIdx.x;
    if (tile < 2048) {   // Pobs
        int mb = tile & 127, nb = tile >> 7;
        gemm_h(sa_u, sb_u, g_obsP, 131072, g_WpostP + 131072, 196608, 1024, mb, nb, acc);
        epi2(mb << 7, nb << 6, acc, [&](int r, int c, float v0, float v1) {
            float2 o = make_float2(v0 + bpost_in[c], v1 + bpost_in[c + 1]);
            *(float2*)&g_Pobs[(size_t)r * HIDv + c] = o;
        });
    } else {             // pre
        tile -= 2048;
        int mb = tile & 127, nb = tile >> 7;
        gemm_h(sa_u, sb_u, g_actP, 8192, g_WrnnP + 16384, 20480, 64, mb, nb, acc);
        epi2(mb << 7, nb << 6, acc, [&](int r, int c, float v0, float v1) {
            float2 o = make_float2(v0 + brnn[c], v1 + brnn[c + 1]);
            *(float2*)&g_pre[(size_t)r * HIDv + c] = o;
        });
    }
}

__global__ __launch_bounds__(256)
void rf_k(const float* __restrict__ bprior_in) {
    extern __shared__ char dyn[];
    uint32_t sa_u = smem_u32(dyn), sb_u = sa_u + NSTAGE * 8192;
    float acc[2][4][4];
    int tile = blockIdx.x;           // 2048
    int low = tile & 127, t = low >> 1, mb = low & 1, nb = tile >> 7;
    gemm_h(sa_u, sb_u, g_hrP + (size_t)t * 524288, 262144, g_WpriorP, 131072,
           2048, mb, nb, acc);
    __half* out = g_rfP + (size_t)t * 262144;
    epi2(mb << 7, nb << 6, acc, [&](int r, int c, float v0, float v1) {
        v0 = fmaxf(v0 + bprior_in[c], 0.f);
        v1 = fmaxf(v1 + bprior_in[c + 1], 0.f);
        *(__half2*)&out[apack(r, c, 131072)] = __floats2half2_rn(v0, v1);
    });
}

__global__ __launch_bounds__(256)
void ms_k(const float* __restrict__ bprior_ms,
          float* __restrict__ qm_o, float* __restrict__ qs_o) {
    extern __shared__ char dyn[];
    uint32_t sa_u = smem_u32(dyn), sb_u = sa_u + NSTAGE * 8192;
    float acc[2][4][4];
    int tile = blockIdx.x;           // 1024
    int low = tile & 127, t = low >> 1, mb = low & 1, nb = tile >> 7;
    gemm_h(sa_u, sb_u, g_rfP + (size_t)t * 262144, 131072, g_WpriormsP, 65536,
           1024, mb, nb, acc);
    int bn0 = nb << 6;
    if (bn0 < STOv) {
        epi2(mb << 7, bn0, acc, [&](int r, int c, float v0, float v1) {
            size_t o = ((size_t)r * Tv + t) * STOv + c;
            *(float2*)&qm_o[o] = make_float2(v0 + bprior_ms[c], v1 + bprior_ms[c + 1]);
        });
    } else {
        epi2(mb << 7, bn0, acc, [&](int r, int c, float v0, float v1) {
            size_t o = ((size_t)r * Tv + t) * STOv + (c - STOv);
            *(float2*)&qs_o[o] = make_float2(softplusf(v0 + bprior_ms[c]) + 0.1f,
                                             softplusf(v1 + bprior_ms[c + 1]) + 0.1f);
        });
    }
}

// --------------------------- persistent scan kernel -------------------------
struct ScanArgs {
    const float* noise;
    const float* bih; const float* bhh;
    const float* bpost_ms;
    float* h_o; float* z_o; float* pm_o; float* ps_o;
    int nb;
};

__global__ __launch_bounds__(256)
void scan_k(ScanArgs a) {
    extern __shared__ char dyn[];
    uint32_t sa_u = smem_u32(dyn), sb_u = sa_u + NSTAGE * 8192;
    const int nb = a.nb;
    float acc[2][4][4];
    const size_t GHS = (size_t)Bv * 3 * DETv;

    for (int t = 0; t < Tv; t++) {
        // ---- P1: rnn = relu(z_prev @ Wz + pre_t)   32 tiles, K=256
        {
            const __half* Az = t ? g_zrP : g_zeroH;
            int mstr = t ? 32768 : 0;
            for (int tile = blockIdx.x; tile < 32; tile += nb) {
                int mb = tile & 1, nbt = tile >> 1;
                gemm_h(sa_u, sb_u, Az, mstr, g_WrnnP, 20480, 256, mb, nbt, acc);
                epi2(mb << 7, nbt << 6, acc, [&](int r, int c, float v0, float v1) {
                    float2 p = *(const float2*)&g_pre[((size_t)r * Tv + t) * HIDv + c];
                    v0 = fmaxf(v0 + p.x, 0.f);
                    v1 = fmaxf(v1 + p.y, 0.f);
                    *(__half2*)&g_rnnP[apack(r, c, 131072)] = __floats2half2_rn(v0, v1);
                });
            }
        }
        gridbar(nb);

        // ---- P2: 576 uniform K=1024 tiles (gi 192 + gh 2x192)
        {
            for (int tile = blockIdx.x; tile < 576; tile += nb) {
                if (tile < 192) {
                    int mb = tile & 1, nbt = tile >> 1;
                    gemm_h(sa_u, sb_u, g_rnnP, 131072, g_WihP, 65536, 1024, mb, nbt, acc);
                    epi2(mb << 7, nbt << 6, acc, [&](int r, int c, float v0, float v1) {
                        *(float2*)&g_gi[(size_t)r * (3 * DETv) + c] =
                            make_float2(v0 + a.bih[c], v1 + a.bih[c + 1]);
                    });
                } else {
                    int u = tile - 192, kh = u / 192, v2 = u % 192;
                    int mb = v2 & 1, nbt = v2 >> 1;
                    const __half* Ah = t ? g_hrP + (size_t)(t - 1) * 524288 + kh * 131072
                                         : g_zeroH;
                    int mstr = t ? 262144 : 0;
                    float* outp = g_gh + (size_t)kh * GHS;
                    gemm_h(sa_u, sb_u, Ah, mstr, g_WhhP + (size_t)kh * 65536, 131072,
                           1024, mb, nbt, acc);
                    epi2(mb << 7, nbt << 6, acc, [&](int r, int c, float v0, float v1) {
                        *(float2*)&outp[(size_t)r * (3 * DETv) + c] = make_float2(v0, v1);
                    });
                }
            }
        }
        gridbar(nb);

        // ---- P3: GRU (gh reduce fused) -> h_t fp32 + g_hrP half
        {
            const float* hp = t ? a.h_o + (size_t)(t - 1) * DETv : g_zero;
            size_t hps = t ? (size_t)Tv * DETv : 0;
            __half* hrp = g_hrP + (size_t)t * 524288;
            for (int idx = blockIdx.x * 256 + threadIdx.x; idx < Bv * DETv / 2;
                 idx += nb * 256) {
                int m = idx >> 10, j = (idx & 1023) * 2;
                size_t base = (size_t)m * (3 * DETv) + j;
                float2 gi0 = *(const float2*)&g_gi[base];
                float2 gi1 = *(const float2*)&g_gi[base + DETv];
                float2 gi2 = *(const float2*)&g_gi[base + 2 * DETv];
                float2 ga0 = *(const float2*)&g_gh[base];
                float2 ga1 = *(const float2*)&g_gh[base + DETv];
                float2 ga2 = *(const float2*)&g_gh[base + 2 * DETv];
                float2 gb0 = *(const float2*)&g_gh[GHS + base];
                float2 gb1 = *(const float2*)&g_gh[GHS + base + DETv];
                float2 gb2 = *(const float2*)&g_gh[GHS + base + 2 * DETv];
                float2 bh0 = *(const float2*)&a.bhh[j];
                float2 bh1 = *(const float2*)&a.bhh[DETv + j];
                float2 bh2 = *(const float2*)&a.bhh[2 * DETv + j];
                float2 hpv = *(const float2*)&hp[(size_t)m * hps + j];
                float r0 = sigmoidf(gi0.x + ga0.x + gb0.x + bh0.x);
                float r1 = sigmoidf(gi0.y + ga0.y + gb0.y + bh0.y);
                float u0 = sigmoidf(gi1.x + ga1.x + gb1.x + bh1.x);
                float u1 = sigmoidf(gi1.y + ga1.y + gb1.y + bh1.y);
                float n0 = tanhf(gi2.x + r0 * (ga2.x + gb2.x + bh2.x));
                float n1 = tanhf(gi2.y + r1 * (ga2.y + gb2.y + bh2.y));
                float h0 = (1.f - u0) * n0 + u0 * hpv.x;
                float h1 = (1.f - u1) * n1 + u1 * hpv.y;
                *(float2*)&a.h_o[((size_t)m * Tv + t) * DETv + j] = make_float2(h0, h1);
                *(__half2*)&hrp[apack(m, j, 262144)] = __floats2half2_rn(h0, h1);
            }
        }
        gridbar(nb);

        // ---- P4a: pf split-K partials (128 tiles: 4ks x 32, K=512)
        for (int tile = blockIdx.x; tile < 128; tile += nb) {
            int ks = tile >> 5, rem = tile & 31;
            int mb = rem & 1, nbt = rem >> 1;
            gemm_h(sa_u, sb_u, g_hrP + (size_t)t * 524288 + ks * 65536, 262144,
                   g_WpostP + ks * 32768, 196608, 512, mb, nbt, acc);
            float* outp = g_p4 + (size_t)ks * Bv * HIDv;
            epi2(mb << 7, nbt << 6, acc, [&](int r, int c, float v0, float v1) {
                *(float2*)&outp[(size_t)r * HIDv + c] = make_float2(v0, v1);
            });
        }
        gridbar(nb);

        // ---- P4b: reduce + Pobs + relu -> g_pfP
        for (int idx = blockIdx.x * 256 + threadIdx.x; idx < Bv * HIDv / 2;
             idx += nb * 256) {
            int m = idx >> 9, j = (idx & 511) * 2;
            size_t i2 = (size_t)m * HIDv + j;
            const size_t S = (size_t)Bv * HIDv;
            float2 s0 = *(const float2*)&g_p4[i2];
            float2 s1 = *(const float2*)&g_p4[S + i2];
            float2 s2 = *(const float2*)&g_p4[2 * S + i2];
            float2 s3 = *(const float2*)&g_p4[3 * S + i2];
            float2 po = *(const float2*)&g_Pobs[((size_t)m * Tv + t) * HIDv + j];
            float v0 = fmaxf(s0.x + s1.x + s2.x + s3.x + po.x, 0.f);
            float v1 = fmaxf(s0.y + s1.y + s2.y + s3.y + po.y, 0.f);
            *(__half2*)&g_pfP[apack(m, j, 131072)] = __floats2half2_rn(v0, v1);
        }
        gridbar(nb);

        // ---- P5a: [pm|ps] split-K partials (64 tiles: 4ks x 16, K=256)
        for (int tile = blockIdx.x; tile < 64; tile += nb) {
            int ks = tile >> 4, rem = tile & 15;
            int mb = rem & 1, nbt = rem >> 1;
            gemm_h(sa_u, sb_u, g_pfP + ks * 32768, 131072,
                   g_WpostmsP + ks * 16384, 65536, 256, mb, nbt, acc);
            float* outp = g_p5 + (size_t)ks * Bv * 2 * STOv;
            epi2(mb << 7, nbt << 6, acc, [&](int r, int c, float v0, float v1) {
                *(float2*)&outp[(size_t)r * (2 * STOv) + c] = make_float2(v0, v1);
            });
        }
        gridbar(nb);

        // ---- P5b: pm, ps, z + g_zrP
        for (int idx = blockIdx.x * 256 + threadIdx.x; idx < Bv * STOv / 2;
             idx += nb * 256) {
            int m = idx >> 7, j = (idx & 127) * 2;
            size_t b0 = (size_t)m * (2 * STOv);
            const size_t S = (size_t)Bv * (2 * STOv);
            float2 pmv = make_float2(a.bpost_ms[j], a.bpost_ms[j + 1]);
            float2 srv = make_float2(a.bpost_ms[STOv + j], a.bpost_ms[STOv + j + 1]);
#pragma unroll
            for (int ks = 0; ks < 4; ks++) {
                float2 x0 = *(const float2*)&g_p5[ks * S + b0 + j];
                float2 x1 = *(const float2*)&g_p5[ks * S + b0 + STOv + j];
                pmv.x += x0.x; pmv.y += x0.y;
                srv.x += x1.x; srv.y += x1.y;
            }
            float ps0 = softplusf(srv.x) + 0.1f;
            float ps1 = softplusf(srv.y) + 0.1f;
            size_t o = ((size_t)m * Tv + t) * STOv + j;
            float2 nz = *(const float2*)&a.noise[o];
            float z0 = pmv.x + ps0 * nz.x;
            float z1 = pmv.y + ps1 * nz.y;
            *(float2*)&a.pm_o[o] = pmv;
            *(float2*)&a.ps_o[o] = make_float2(ps0, ps1);
            *(float2*)&a.z_o[o] = make_float2(z0, z1);
            *(__half2*)&g_zrP[apack(m, j, 32768)] = __floats2half2_rn(z0, z1);
        }
        gridbar(nb);
    }
}

// ------------------------------- launch -------------------------------------
extern "C" void kernel_launch(void* const* d_in, const int* in_sizes, int n_in,
                              void* d_out, int out_size) {
    const float* obs      = (const float*)d_in[0];
    const float* act      = (const float*)d_in[1];
    const float* noise    = (const float*)d_in[4];
    const float* Wrnn     = (const float*)d_in[5];
    const float* brnn     = (const float*)d_in[6];
    const float* Wih      = (const float*)d_in[7];
    const float* Whh      = (const float*)d_in[8];
    const float* bih      = (const float*)d_in[9];
    const float* bhh      = (const float*)d_in[10];
    const float* Wpost_in = (const float*)d_in[11];
    const float* bpost_in = (const float*)d_in[12];
    const float* Wpost_ms = (const float*)d_in[13];
    const float* bpost_ms = (const float*)d_in[14];
    const float* Wprior_in= (const float*)d_in[15];
    const float* bprior_in= (const float*)d_in[16];
    const float* Wprior_ms= (const float*)d_in[17];
    const float* bprior_ms= (const float*)d_in[18];

    float* out  = (float*)d_out;
    float* h_o  = out;
    float* z_o  = h_o + (size_t)BTv * DETv;
    float* pm_o = z_o + (size_t)BTv * STOv;
    float* ps_o = pm_o + (size_t)BTv * STOv;
    float* qm_o = ps_o + (size_t)BTv * STOv;
    float* qs_o = qm_o + (size_t)BTv * STOv;

    cudaFuncSetAttribute(prep_k, cudaFuncAttributeMaxDynamicSharedMemorySize, DYN_SMEM);
    cudaFuncSetAttribute(rf_k,   cudaFuncAttributeMaxDynamicSharedMemorySize, DYN_SMEM);
    cudaFuncSetAttribute(ms_k,   cudaFuncAttributeMaxDynamicSharedMemorySize, DYN_SMEM);
    cudaFuncSetAttribute(scan_k, cudaFuncAttributeMaxDynamicSharedMemorySize, DYN_SMEM);

    int nsm = 0, maxb = 0;
    cudaDeviceGetAttribute(&nsm, cudaDevAttrMultiProcessorCount, 0);
    if (nsm <= 0) nsm = 148;
    cudaOccupancyMaxActiveBlocksPerMultiprocessor(&maxb, scan_k, 256, DYN_SMEM);
    if (maxb > 4) maxb = 4;
    if (maxb == 3) maxb = 2;   // avoid 576-tile imbalance at 3/SM
    if (maxb < 1) maxb = 1;
    int nb = nsm * maxb;

    // launches: 1 packB, 2 packA, 3 prep, 4 scan (<- ncu capture lands on 4th), 5 rf, 6 ms
    packB_k<<<24896, 256>>>(Wrnn, Wih, Whh, Wpost_in, Wpost_ms, Wprior_in, Wprior_ms);
    packA_k<<<8704, 256>>>(obs, act);
    prep_k<<<4096, 256, DYN_SMEM>>>(bpost_in, brnn);

    ScanArgs a;
    a.noise = noise;
    a.bih = bih; a.bhh = bhh;
    a.bpost_ms = bpost_ms;
    a.h_o = h_o; a.z_o = z_o; a.pm_o = pm_o; a.ps_o = ps_o;
    a.nb = nb;
    scan_k<<<nb, 256, DYN_SMEM>>>(a);

    rf_k<<<2048, 256, DYN_SMEM>>>(bprior_in);
    ms_k<<<1024, 256, DYN_SMEM>>>(bprior_ms, qm_o, qs_o);
}

// round 14
// speedup vs baseline: 3.7878x; 1.0399x over previous
#include <cuda_runtime.h>
#include <cuda_fp16.h>
#include <cstdint>
#include <cstddef>

// ---------------------------------------------------------------------------
// RSSM scan: B=256, T=64, A=64, E=1024, HID=1024, DET=2048, STO=256
// fp16 m16n8k16 mma, fragment-packed operands, BK=64 3-stage cp.async pipeline.
// ---------------------------------------------------------------------------

#define Bv   256
#define Tv   64
#define BTv  (Bv*Tv)          // 16384
#define Av   64
#define Ev   1024
#define HIDv 1024
#define DETv 2048
#define STOv 256

#define NSTAGE 3
#define A_STAGE 16384         // bytes: 128 rows x 64 k halves
#define B_STAGE 8192          // bytes: 64 rows x 64 k halves
#define DYN_SMEM (NSTAGE * (A_STAGE + B_STAGE))   // 73728

// ------------------------- device scratch (no allocs) ----------------------
__device__ __align__(16) float g_Pobs[BTv * HIDv];
__device__ __align__(16) float g_pre [BTv * HIDv];
__device__ __align__(16) float g_gi  [Bv * 3 * DETv];
__device__ __align__(16) float g_gh  [2 * Bv * 3 * DETv];
__device__ __align__(16) float g_p4  [4 * Bv * HIDv];
__device__ __align__(16) float g_p5  [4 * Bv * 2 * STOv];
__device__ __align__(16) float g_zero[DETv];              // zeros (fp32)
// packed fp16 activations (mma-A fragment layout)
__device__ __align__(16) __half g_obsP[BTv * Ev];
__device__ __align__(16) __half g_actP[BTv * Av];
__device__ __align__(16) __half g_hrP [(size_t)Tv * 2 * 128 * 2048];
__device__ __align__(16) __half g_rfP [(size_t)Tv * 2 * 64 * 2048];
__device__ __align__(16) __half g_rnnP[2 * 64 * 2048];
__device__ __align__(16) __half g_pfP [2 * 64 * 2048];
__device__ __align__(16) __half g_zrP [2 * 16 * 2048];
__device__ __align__(16) __half g_zeroH[131072];
// packed fp16 weights (mma-B fragment layout, swizzled)
__device__ __align__(16) __half g_WrnnP   [16 * 20 * 1024];
__device__ __align__(16) __half g_WihP    [96 * 64 * 1024];
__device__ __align__(16) __half g_WhhP    [(size_t)96 * 128 * 1024];
__device__ __align__(16) __half g_WpostP  [16 * 192 * 1024];
__device__ __align__(16) __half g_WpostmsP[8 * 64 * 1024];
__device__ __align__(16) __half g_WpriorP [16 * 128 * 1024];
__device__ __align__(16) __half g_WpriormsP[8 * 64 * 1024];
__device__ unsigned g_barcnt;
__device__ unsigned g_bargen;

// ------------------------------- helpers -----------------------------------
__device__ __forceinline__ float softplusf(float x) {
    return (x > 20.f) ? x : log1pf(expf(x));
}
__device__ __forceinline__ float sigmoidf(float x) {
    return 1.f / (1.f + expf(-x));
}
__device__ __forceinline__ uint32_t smem_u32(const void* p) {
    uint32_t a;
    asm("{ .reg .u64 t; cvta.to.shared.u64 t, %1; cvt.u32.u64 %0, t; }"
        : "=r"(a) : "l"(p));
    return a;
}
__device__ __forceinline__ void cpa16(uint32_t dst, const void* src) {
    size_t g = __cvta_generic_to_global(src);
    asm volatile("cp.async.cg.shared.global [%0], [%1], 16;"
                 :: "r"(dst), "l"(g) : "memory");
}
__device__ __forceinline__ void cpa_commit() {
    asm volatile("cp.async.commit_group;" ::: "memory");
}
__device__ __forceinline__ void mma16(float c[4], const uint32_t a[4],
                                      uint32_t b0, uint32_t b1) {
    asm volatile(
        "mma.sync.aligned.m16n8k16.row.col.f32.f16.f16.f32 "
        "{%0,%1,%2,%3},{%4,%5,%6,%7},{%8,%9},{%0,%1,%2,%3};\n"
        : "+f"(c[0]), "+f"(c[1]), "+f"(c[2]), "+f"(c[3])
        : "r"(a[0]), "r"(a[1]), "r"(a[2]), "r"(a[3]), "r"(b0), "r"(b1));
}
#define LDS128(r0, r1, r2, r3, addr) \
    asm volatile("ld.shared.v4.b32 {%0,%1,%2,%3}, [%4];" \
                 : "=r"(r0), "=r"(r1), "=r"(r2), "=r"(r3) : "r"(addr))

// packed-A index (halves) for (m, k even); pair (k, k+1) contiguous
__device__ __forceinline__ int apack(int m, int k, int mbStr) {
    int mb = m >> 7, m1 = m & 127;
    int wm = m1 >> 5, r = m1 & 31;
    int mf = (r >> 4) & 1, p8 = (r >> 3) & 1, g = r & 7;
    int kb = k >> 4, k1 = k & 15;
    int kk8 = k1 >> 3, tig = (k1 >> 1) & 3;
    int lane = g * 4 + tig;
    return mb * mbStr + kb * 2048 + ((wm * 2 + mf) * 32 + lane) * 8 + (p8 + 2 * kk8) * 2;
}

// ---------------------------- grid-wide barrier -----------------------------
__device__ __forceinline__ void gridbar(int nb) {
    __syncthreads();
    if (threadIdx.x == 0) {
        __threadfence();
        unsigned gen;
        asm volatile("ld.acquire.gpu.u32 %0, [%1];" : "=r"(gen) : "l"(&g_bargen) : "memory");
        unsigned arr = atomicAdd(&g_barcnt, 1u);
        if (arr == (unsigned)nb - 1u) {
            atomicExch(&g_barcnt, 0u);
            __threadfence();
            atomicAdd(&g_bargen, 1u);
        } else {
            unsigned cur;
            do {
                asm volatile("ld.acquire.gpu.u32 %0, [%1];" : "=r"(cur) : "l"(&g_bargen) : "memory");
            } while (cur == gen);
        }
        __threadfence();
    }
    __syncthreads();
}

// ------------------------------- GEMM core ----------------------------------
// acc[128x64] += A_packed x B_packed.  K multiple of 64.
// A: [mb][kb16][2048] fragment-packed. B: [nb][kb16][1024] packed+swizzled.
// BK=64 per pipeline stage (2 x k32 sub-chunks per sync round), 3 stages.
__device__ void gemm_h(uint32_t sa_u, uint32_t sb_u,
                       const __half* __restrict__ A, int mbStrA,
                       const __half* __restrict__ B, int nbStrB,
                       int K, int mb, int nb, float acc[2][4][4]) {
    const int tid = threadIdx.x;
    const __half* AP = A + (size_t)mb * mbStrA + tid * 8;
    const __half* BP = B + (size_t)nb * nbStrB + tid * 8;

#pragma unroll
    for (int i = 0; i < 2; i++)
#pragma unroll
        for (int j = 0; j < 4; j++)
#pragma unroll
            for (int c = 0; c < 4; c++) acc[i][j][c] = 0.f;

    auto load_stage = [&](int s, int kt) {   // kt in BK64 units
        const __half* A0 = AP + (size_t)kt * 8192;
        cpa16(sa_u + s * A_STAGE + tid * 16, A0);
        cpa16(sa_u + s * A_STAGE + 4096 + tid * 16, A0 + 2048);
        cpa16(sa_u + s * A_STAGE + 8192 + tid * 16, A0 + 4096);
        cpa16(sa_u + s * A_STAGE + 12288 + tid * 16, A0 + 6144);
        const __half* B0 = BP + (size_t)kt * 4096;
        cpa16(sb_u + s * B_STAGE + tid * 16, B0);
        cpa16(sb_u + s * B_STAGE + 4096 + tid * 16, B0 + 2048);
        cpa_commit();
    };

    const int nk = K >> 6;
#pragma unroll
    for (int s = 0; s < NSTAGE - 1; s++) {
        if (s < nk) load_stage(s, s);
        else cpa_commit();
    }

    const int lane = tid & 31, w = tid >> 5;
    const int wm = w >> 1, wn = w & 1;
    uint32_t aoff0 = (uint32_t)(((wm * 2 + 0) * 32 + lane) * 16);
    uint32_t aoff1 = (uint32_t)(((wm * 2 + 1) * 32 + lane) * 16);
    uint32_t blog = (uint32_t)((wn * 32 + lane) * 32);
    uint32_t bph0 = blog ^ (((blog >> 7) & 1u) << 4);

    int scomp = 0, sload = NSTAGE - 1;
    for (int kt = 0; kt < nk; kt++) {
        asm volatile("cp.async.wait_group %0;" :: "n"(NSTAGE - 2) : "memory");
        __syncthreads();
        if (kt + NSTAGE - 1 < nk) load_stage(sload, kt + NSTAGE - 1);
        else cpa_commit();
        if (++sload == NSTAGE) sload = 0;
        uint32_t sA = sa_u + scomp * A_STAGE;
        uint32_t sB = sb_u + scomp * B_STAGE;
        if (++scomp == NSTAGE) scomp = 0;
#pragma unroll
        for (int c = 0; c < 2; c++) {       // two k32 sub-chunks per stage
#pragma unroll
            for (int x = 0; x < 2; x++) {
                uint32_t aR[2][4], bR[8];
                LDS128(aR[0][0], aR[0][1], aR[0][2], aR[0][3],
                       sA + c * 8192 + x * 4096 + aoff0);
                LDS128(aR[1][0], aR[1][1], aR[1][2], aR[1][3],
                       sA + c * 8192 + x * 4096 + aoff1);
                LDS128(bR[0], bR[1], bR[2], bR[3], sB + c * 4096 + x * 2048 + bph0);
                LDS128(bR[4], bR[5], bR[6], bR[7],
                       sB + c * 4096 + x * 2048 + (bph0 ^ 16u));
#pragma unroll
                for (int mf = 0; mf < 2; mf++)
#pragma unroll
                    for (int nf = 0; nf < 4; nf++)
                        mma16(acc[mf][nf], aR[mf], bR[nf * 2], bR[nf * 2 + 1]);
            }
        }
    }
    __syncthreads();
}

// epilogue: per (row, even col) pair
template <typename F>
__device__ __forceinline__ void epi2(int bm0, int bn0, float acc[2][4][4], F&& f) {
    const int tid = threadIdx.x;
    const int lane = tid & 31, w = tid >> 5;
    const int wm = w >> 1, wn = w & 1;
    const int g = lane >> 2, tig = lane & 3;
#pragma unroll
    for (int mf = 0; mf < 2; mf++)
#pragma unroll
        for (int nf = 0; nf < 4; nf++)
#pragma unroll
            for (int h = 0; h < 2; h++) {
                int row = bm0 + wm * 32 + mf * 16 + g + h * 8;
                int col = bn0 + wn * 32 + nf * 8 + tig * 2;
                f(row, col, acc[mf][nf][h * 2], acc[mf][nf][h * 2 + 1]);
            }
}

// ---------------------------- pack kernels ----------------------------------
__global__ __launch_bounds__(256)
void packB_k(const float* __restrict__ Wrnn, const float* __restrict__ Wih,
             const float* __restrict__ Whh, const float* __restrict__ Wpost,
             const float* __restrict__ Wpostms, const float* __restrict__ Wprior,
             const float* __restrict__ Wpriorms) {
    int b = blockIdx.x;
    const float* src; __half* dst; int N, K; bool KN;
    if (b < 320)        { src = Wrnn;     dst = g_WrnnP;     N = 1024; K = 320;  KN = true;  }
    else if (b < 6464)  { b -= 320;  src = Wih;     dst = g_WihP;     N = 6144; K = 1024; KN = false; }
    else if (b < 18752) { b -= 6464; src = Whh;     dst = g_WhhP;     N = 6144; K = 2048; KN = false; }
    else if (b < 21824) { b -= 18752; src = Wpost;  dst = g_WpostP;   N = 1024; K = 3072; KN = true;  }
    else if (b < 22336) { b -= 21824; src = Wpostms; dst = g_WpostmsP; N = 512; K = 1024; KN = true;  }
    else if (b < 24384) { b -= 22336; src = Wprior; dst = g_WpriorP;  N = 1024; K = 2048; KN = true;  }
    else                { b -= 24384; src = Wpriorms; dst = g_WpriormsP; N = 512; K = 1024; KN = true; }
    int nkb = K >> 4;
    int nb = b / nkb, kb = b % nkb;
    int tid = threadIdx.x;
    int nf = tid & 3, wl = tid >> 2;
    int lane = wl & 31, wn = wl >> 5;
    int g = lane >> 2, tig = lane & 3;
    int n = nb * 64 + wn * 32 + nf * 8 + g;
    uint32_t swz = (((uint32_t)(tid * 8) >> 7) & 1u) << 4;
    char* blk = (char*)dst + (size_t)b * 2048;
#pragma unroll
    for (int reg = 0; reg < 2; reg++) {
        int k = kb * 16 + reg * 8 + tig * 2;
        float v0 = KN ? src[(size_t)k * N + n] : src[(size_t)n * K + k];
        float v1 = KN ? src[(size_t)(k + 1) * N + n] : src[(size_t)n * K + k + 1];
        uint32_t phys = (uint32_t)(tid * 8 + reg * 4) ^ swz;
        *(__half2*)(blk + phys) = __floats2half2_rn(v0, v1);
    }
}

__global__ __launch_bounds__(256)
void packA_k(const float* __restrict__ obs, const float* __restrict__ act) {
    int b = blockIdx.x;
    int tid = threadIdx.x;
    int lane = tid & 31, mfwm = tid >> 5;
    int mf = mfwm & 1, wm = mfwm >> 1;
    int g = lane >> 2, tig = lane & 3;
    if (b < 8192) {
        int mb = b >> 6, kb = b & 63;
        __half2* dst = (__half2*)(g_obsP + (size_t)b * 2048) + tid * 4;
#pragma unroll
        for (int r = 0; r < 4; r++) {
            int p8 = r & 1, kk8 = r >> 1;
            int m = mb * 128 + wm * 32 + mf * 16 + p8 * 8 + g;
            int k = kb * 16 + kk8 * 8 + tig * 2;
            float2 v = *(const float2*)&obs[(size_t)m * 1024 + k];
            dst[r] = __floats2half2_rn(v.x, v.y);
        }
    } else {
        b -= 8192;
        int mb = b >> 2, kb = b & 3;
        __half2* dst = (__half2*)(g_actP + (size_t)b * 2048) + tid * 4;
#pragma unroll
        for (int r = 0; r < 4; r++) {
            int p8 = r & 1, kk8 = r >> 1;
            int m = mb * 128 + wm * 32 + mf * 16 + p8 * 8 + g;
            int k = kb * 16 + kk8 * 8 + tig * 2;
            int t = m & 63;
            float2 v = make_float2(0.f, 0.f);
            if (t) v = *(const float2*)&act[(size_t)(m - 1) * 64 + k];
            dst[r] = __floats2half2_rn(v.x, v.y);
        }
    }
}

// --------------------------- batched pre / post -----------------------------
__global__ __launch_bounds__(256)
void prep_k(const float* __restrict__ bpost_in, const float* __restrict__ brnn) {
    extern __shared__ char dyn[];
    uint32_t sa_u = smem_u32(dyn), sb_u = sa_u + NSTAGE * A_STAGE;
    float acc[2][4][4];
    int tile = blockIdx.x;
    if (tile < 2048) {   // Pobs
        int mb = tile & 127, nb = tile >> 7;
        gemm_h(sa_u, sb_u, g_obsP, 131072, g_WpostP + 131072, 196608, 1024, mb, nb, acc);
        epi2(mb << 7, nb << 6, acc, [&](int r, int c, float v0, float v1) {
            float2 o = make_float2(v0 + bpost_in[c], v1 + bpost_in[c + 1]);
            *(float2*)&g_Pobs[(size_t)r * HIDv + c] = o;
        });
    } else {             // pre
        tile -= 2048;
        int mb = tile & 127, nb = tile >> 7;
        gemm_h(sa_u, sb_u, g_actP, 8192, g_WrnnP + 16384, 20480, 64, mb, nb, acc);
        epi2(mb << 7, nb << 6, acc, [&](int r, int c, float v0, float v1) {
            float2 o = make_float2(v0 + brnn[c], v1 + brnn[c + 1]);
            *(float2*)&g_pre[(size_t)r * HIDv + c] = o;
        });
    }
}

__global__ __launch_bounds__(256)
void rf_k(const float* __restrict__ bprior_in) {
    extern __shared__ char dyn[];
    uint32_t sa_u = smem_u32(dyn), sb_u = sa_u + NSTAGE * A_STAGE;
    float acc[2][4][4];
    int tile = blockIdx.x;           // 2048
    int low = tile & 127, t = low >> 1, mb = low & 1, nb = tile >> 7;
    gemm_h(sa_u, sb_u, g_hrP + (size_t)t * 524288, 262144, g_WpriorP, 131072,
           2048, mb, nb, acc);
    __half* out = g_rfP + (size_t)t * 262144;
    epi2(mb << 7, nb << 6, acc, [&](int r, int c, float v0, float v1) {
        v0 = fmaxf(v0 + bprior_in[c], 0.f);
        v1 = fmaxf(v1 + bprior_in[c + 1], 0.f);
        *(__half2*)&out[apack(r, c, 131072)] = __floats2half2_rn(v0, v1);
    });
}

__global__ __launch_bounds__(256)
void ms_k(const float* __restrict__ bprior_ms,
          float* __restrict__ qm_o, float* __restrict__ qs_o) {
    extern __shared__ char dyn[];
    uint32_t sa_u = smem_u32(dyn), sb_u = sa_u + NSTAGE * A_STAGE;
    float acc[2][4][4];
    int tile = blockIdx.x;           // 1024
    int low = tile & 127, t = low >> 1, mb = low & 1, nb = tile >> 7;
    gemm_h(sa_u, sb_u, g_rfP + (size_t)t * 262144, 131072, g_WpriormsP, 65536,
           1024, mb, nb, acc);
    int bn0 = nb << 6;
    if (bn0 < STOv) {
        epi2(mb << 7, bn0, acc, [&](int r, int c, float v0, float v1) {
            size_t o = ((size_t)r * Tv + t) * STOv + c;
            *(float2*)&qm_o[o] = make_float2(v0 + bprior_ms[c], v1 + bprior_ms[c + 1]);
        });
    } else {
        epi2(mb << 7, bn0, acc, [&](int r, int c, float v0, float v1) {
            size_t o = ((size_t)r * Tv + t) * STOv + (c - STOv);
            *(float2*)&qs_o[o] = make_float2(softplusf(v0 + bprior_ms[c]) + 0.1f,
                                             softplusf(v1 + bprior_ms[c + 1]) + 0.1f);
        });
    }
}

// --------------------------- persistent scan kernel -------------------------
struct ScanArgs {
    const float* noise;
    const float* bih; const float* bhh;
    const float* bpost_ms;
    float* h_o; float* z_o; float* pm_o; float* ps_o;
    int nb;
};

__global__ __launch_bounds__(256)
void scan_k(ScanArgs a) {
    extern __shared__ char dyn[];
    uint32_t sa_u = smem_u32(dyn), sb_u = sa_u + NSTAGE * A_STAGE;
    const int nb = a.nb;
    float acc[2][4][4];
    const size_t GHS = (size_t)Bv * 3 * DETv;

    for (int t = 0; t < Tv; t++) {
        // ---- P1: rnn = relu(z_prev @ Wz + pre_t)   32 tiles, K=256
        {
            const __half* Az = t ? g_zrP : g_zeroH;
            int mstr = t ? 32768 : 0;
            for (int tile = blockIdx.x; tile < 32; tile += nb) {
                int mb = tile & 1, nbt = tile >> 1;
                gemm_h(sa_u, sb_u, Az, mstr, g_WrnnP, 20480, 256, mb, nbt, acc);
                epi2(mb << 7, nbt << 6, acc, [&](int r, int c, float v0, float v1) {
                    float2 p = *(const float2*)&g_pre[((size_t)r * Tv + t) * HIDv + c];
                    v0 = fmaxf(v0 + p.x, 0.f);
                    v1 = fmaxf(v1 + p.y, 0.f);
                    *(__half2*)&g_rnnP[apack(r, c, 131072)] = __floats2half2_rn(v0, v1);
                });
            }
        }
        gridbar(nb);

        // ---- P2: 576 uniform K=1024 tiles (gi 192 + gh 2x192)
        {
            for (int tile = blockIdx.x; tile < 576; tile += nb) {
                if (tile < 192) {
                    int mb = tile & 1, nbt = tile >> 1;
                    gemm_h(sa_u, sb_u, g_rnnP, 131072, g_WihP, 65536, 1024, mb, nbt, acc);
                    epi2(mb << 7, nbt << 6, acc, [&](int r, int c, float v0, float v1) {
                        *(float2*)&g_gi[(size_t)r * (3 * DETv) + c] =
                            make_float2(v0 + a.bih[c], v1 + a.bih[c + 1]);
                    });
                } else {
                    int u = tile - 192, kh = u / 192, v2 = u % 192;
                    int mb = v2 & 1, nbt = v2 >> 1;
                    const __half* Ah = t ? g_hrP + (size_t)(t - 1) * 524288 + kh * 131072
                                         : g_zeroH;
                    int mstr = t ? 262144 : 0;
                    float* outp = g_gh + (size_t)kh * GHS;
                    gemm_h(sa_u, sb_u, Ah, mstr, g_WhhP + (size_t)kh * 65536, 131072,
                           1024, mb, nbt, acc);
                    epi2(mb << 7, nbt << 6, acc, [&](int r, int c, float v0, float v1) {
                        *(float2*)&outp[(size_t)r * (3 * DETv) + c] = make_float2(v0, v1);
                    });
                }
            }
        }
        gridbar(nb);

        // ---- P3: GRU (gh reduce fused) -> h_t fp32 + g_hrP half
        {
            const float* hp = t ? a.h_o + (size_t)(t - 1) * DETv : g_zero;
            size_t hps = t ? (size_t)Tv * DETv : 0;
            __half* hrp = g_hrP + (size_t)t * 524288;
            for (int idx = blockIdx.x * 256 + threadIdx.x; idx < Bv * DETv / 2;
                 idx += nb * 256) {
                int m = idx >> 10, j = (idx & 1023) * 2;
                size_t base = (size_t)m * (3 * DETv) + j;
                float2 gi0 = *(const float2*)&g_gi[base];
                float2 gi1 = *(const float2*)&g_gi[base + DETv];
                float2 gi2 = *(const float2*)&g_gi[base + 2 * DETv];
                float2 ga0 = *(const float2*)&g_gh[base];
                float2 ga1 = *(const float2*)&g_gh[base + DETv];
                float2 ga2 = *(const float2*)&g_gh[base + 2 * DETv];
                float2 gb0 = *(const float2*)&g_gh[GHS + base];
                float2 gb1 = *(const float2*)&g_gh[GHS + base + DETv];
                float2 gb2 = *(const float2*)&g_gh[GHS + base + 2 * DETv];
                float2 bh0 = *(const float2*)&a.bhh[j];
                float2 bh1 = *(const float2*)&a.bhh[DETv + j];
                float2 bh2 = *(const float2*)&a.bhh[2 * DETv + j];
                float2 hpv = *(const float2*)&hp[(size_t)m * hps + j];
                float r0 = sigmoidf(gi0.x + ga0.x + gb0.x + bh0.x);
                float r1 = sigmoidf(gi0.y + ga0.y + gb0.y + bh0.y);
                float u0 = sigmoidf(gi1.x + ga1.x + gb1.x + bh1.x);
                float u1 = sigmoidf(gi1.y + ga1.y + gb1.y + bh1.y);
                float n0 = tanhf(gi2.x + r0 * (ga2.x + gb2.x + bh2.x));
                float n1 = tanhf(gi2.y + r1 * (ga2.y + gb2.y + bh2.y));
                float h0 = (1.f - u0) * n0 + u0 * hpv.x;
                float h1 = (1.f - u1) * n1 + u1 * hpv.y;
                *(float2*)&a.h_o[((size_t)m * Tv + t) * DETv + j] = make_float2(h0, h1);
                *(__half2*)&hrp[apack(m, j, 262144)] = __floats2half2_rn(h0, h1);
            }
        }
        gridbar(nb);

        // ---- P4a: pf split-K partials (128 tiles: 4ks x 32, K=512)
        for (int tile = blockIdx.x; tile < 128; tile += nb) {
            int ks = tile >> 5, rem = tile & 31;
            int mb = rem & 1, nbt = rem >> 1;
            gemm_h(sa_u, sb_u, g_hrP + (size_t)t * 524288 + ks * 65536, 262144,
                   g_WpostP + ks * 32768, 196608, 512, mb, nbt, acc);
            float* outp = g_p4 + (size_t)ks * Bv * HIDv;
            epi2(mb << 7, nbt << 6, acc, [&](int r, int c, float v0, float v1) {
                *(float2*)&outp[(size_t)r * HIDv + c] = make_float2(v0, v1);
            });
        }
        gridbar(nb);

        // ---- P4b: reduce + Pobs + relu -> g_pfP
        for (int idx = blockIdx.x * 256 + threadIdx.x; idx < Bv * HIDv / 2;
             idx += nb * 256) {
            int m = idx >> 9, j = (idx & 511) * 2;
            size_t i2 = (size_t)m * HIDv + j;
            const size_t S = (size_t)Bv * HIDv;
            float2 s0 = *(const float2*)&g_p4[i2];
            float2 s1 = *(const float2*)&g_p4[S + i2];
            float2 s2 = *(const float2*)&g_p4[2 * S + i2];
            float2 s3 = *(const float2*)&g_p4[3 * S + i2];
            float2 po = *(const float2*)&g_Pobs[((size_t)m * Tv + t) * HIDv + j];
            float v0 = fmaxf(s0.x + s1.x + s2.x + s3.x + po.x, 0.f);
            float v1 = fmaxf(s0.y + s1.y + s2.y + s3.y + po.y, 0.f);
            *(__half2*)&g_pfP[apack(m, j, 131072)] = __floats2half2_rn(v0, v1);
        }
        gridbar(nb);

        // ---- P5a: [pm|ps] split-K partials (64 tiles: 4ks x 16, K=256)
        for (int tile = blockIdx.x; tile < 64; tile += nb) {
            int ks = tile >> 4, rem = tile & 15;
            int mb = rem & 1, nbt = rem >> 1;
            gemm_h(sa_u, sb_u, g_pfP + ks * 32768, 131072,
                   g_WpostmsP + ks * 16384, 65536, 256, mb, nbt, acc);
            float* outp = g_p5 + (size_t)ks * Bv * 2 * STOv;
            epi2(mb << 7, nbt << 6, acc, [&](int r, int c, float v0, float v1) {
                *(float2*)&outp[(size_t)r * (2 * STOv) + c] = make_float2(v0, v1);
            });
        }
        gridbar(nb);

        // ---- P5b: pm, ps, z + g_zrP
        for (int idx = blockIdx.x * 256 + threadIdx.x; idx < Bv * STOv / 2;
             idx += nb * 256) {
            int m = idx >> 7, j = (idx & 127) * 2;
            size_t b0 = (size_t)m * (2 * STOv);
            const size_t S = (size_t)Bv * (2 * STOv);
            float2 pmv = make_float2(a.bpost_ms[j], a.bpost_ms[j + 1]);
            float2 srv = make_float2(a.bpost_ms[STOv + j], a.bpost_ms[STOv + j + 1]);
#pragma unroll
            for (int ks = 0; ks < 4; ks++) {
                float2 x0 = *(const float2*)&g_p5[ks * S + b0 + j];
                float2 x1 = *(const float2*)&g_p5[ks * S + b0 + STOv + j];
                pmv.x += x0.x; pmv.y += x0.y;
                srv.x += x1.x; srv.y += x1.y;
            }
            float ps0 = softplusf(srv.x) + 0.1f;
            float ps1 = softplusf(srv.y) + 0.1f;
            size_t o = ((size_t)m * Tv + t) * STOv + j;
            float2 nz = *(const float2*)&a.noise[o];
            float z0 = pmv.x + ps0 * nz.x;
            float z1 = pmv.y + ps1 * nz.y;
            *(float2*)&a.pm_o[o] = pmv;
            *(float2*)&a.ps_o[o] = make_float2(ps0, ps1);
            *(float2*)&a.z_o[o] = make_float2(z0, z1);
            *(__half2*)&g_zrP[apack(m, j, 32768)] = __floats2half2_rn(z0, z1);
        }
        gridbar(nb);
    }
}

// ------------------------------- launch -------------------------------------
extern "C" void kernel_launch(void* const* d_in, const int* in_sizes, int n_in,
                              void* d_out, int out_size) {
    const float* obs      = (const float*)d_in[0];
    const float* act      = (const float*)d_in[1];
    const float* noise    = (const float*)d_in[4];
    const float* Wrnn     = (const float*)d_in[5];
    const float* brnn     = (const float*)d_in[6];
    const float* Wih      = (const float*)d_in[7];
    const float* Whh      = (const float*)d_in[8];
    const float* bih      = (const float*)d_in[9];
    const float* bhh      = (const float*)d_in[10];
    const float* Wpost_in = (const float*)d_in[11];
    const float* bpost_in = (const float*)d_in[12];
    const float* Wpost_ms = (const float*)d_in[13];
    const float* bpost_ms = (const float*)d_in[14];
    const float* Wprior_in= (const float*)d_in[15];
    const float* bprior_in= (const float*)d_in[16];
    const float* Wprior_ms= (const float*)d_in[17];
    const float* bprior_ms= (const float*)d_in[18];

    float* out  = (float*)d_out;
    float* h_o  = out;
    float* z_o  = h_o + (size_t)BTv * DETv;
    float* pm_o = z_o + (size_t)BTv * STOv;
    float* ps_o = pm_o + (size_t)BTv * STOv;
    float* qm_o = ps_o + (size_t)BTv * STOv;
    float* qs_o = qm_o + (size_t)BTv * STOv;

    cudaFuncSetAttribute(prep_k, cudaFuncAttributeMaxDynamicSharedMemorySize, DYN_SMEM);
    cudaFuncSetAttribute(rf_k,   cudaFuncAttributeMaxDynamicSharedMemorySize, DYN_SMEM);
    cudaFuncSetAttribute(ms_k,   cudaFuncAttributeMaxDynamicSharedMemorySize, DYN_SMEM);
    cudaFuncSetAttribute(scan_k, cudaFuncAttributeMaxDynamicSharedMemorySize, DYN_SMEM);

    int nsm = 0, maxb = 0;
    cudaDeviceGetAttribute(&nsm, cudaDevAttrMultiProcessorCount, 0);
    if (nsm <= 0) nsm = 148;
    cudaOccupancyMaxActiveBlocksPerMultiprocessor(&maxb, scan_k, 256, DYN_SMEM);
    if (maxb > 2) maxb = 2;
    if (maxb < 1) maxb = 1;
    int nb = nsm * maxb;

    // launches: 1 packB, 2 packA, 3 prep, 4 scan (ncu capture), 5 rf, 6 ms
    packB_k<<<24896, 256>>>(Wrnn, Wih, Whh, Wpost_in, Wpost_ms, Wprior_in, Wprior_ms);
    packA_k<<<8704, 256>>>(obs, act);
    prep_k<<<4096, 256, DYN_SMEM>>>(bpost_in, brnn);

    ScanArgs a;
    a.noise = noise;
    a.bih = bih; a.bhh = bhh;
    a.bpost_ms = bpost_ms;
    a.h_o = h_o; a.z_o = z_o; a.pm_o = pm_o; a.ps_o = ps_o;
    a.nb = nb;
    scan_k<<<nb, 256, DYN_SMEM>>>(a);

    rf_k<<<2048, 256, DYN_SMEM>>>(bprior_in);
    ms_k<<<1024, 256, DYN_SMEM>>>(bprior_ms, qm_o, qs_o);
}